// round 2
// baseline (speedup 1.0000x reference)
#include <cuda_runtime.h>
#include <cstdint>

// Problem constants
#define Bb 32
#define Tt 1024
#define AC 20
#define SE 16
#define Hh 64
#define NH 4
#define HD 16
#define NROWS (Bb*Tt)   // 32768

typedef unsigned long long u64;

// ---------------- scratch (device globals; no allocation allowed) ----------------
__device__ float g_Q[Bb*NH*Tt*HD];     // [b][h][t][d], prescaled by 1/sqrt(HD)
__device__ float g_K[Bb*NH*Tt*HD];
__device__ float g_V[Bb*NH*Tt*HD];
__device__ float g_ctx[NROWS*Hh];      // [b*T+t][64]
__device__ float g_enh[NROWS*AC];      // enhanced (pre std-corr)
__device__ float g_part[256*80];       // per-block partial sums (a, a2, e, e2) x 20ch
__device__ float g_mean[AC], g_corr[AC];
// fused weights
__device__ float g_WqE[Hh*SE], g_bqE[Hh];
__device__ float g_WkE[Hh*AC], g_bkE[Hh];
__device__ float g_WvE[Hh*AC], g_bvE[Hh];
__device__ float g_Wop[AC*Hh], g_bop[AC];

// ---------------- f32x2 packed helpers (sm_100+ PTX) ----------------
__device__ __forceinline__ u64 fma2(u64 a, u64 b, u64 c) {
    u64 d;
    asm("fma.rn.f32x2 %0, %1, %2, %3;" : "=l"(d) : "l"(a), "l"(b), "l"(c));
    return d;
}
__device__ __forceinline__ u64 pack2(float lo, float hi) {
    u64 r; asm("mov.b64 %0, {%1,%2};" : "=l"(r) : "f"(lo), "f"(hi)); return r;
}
__device__ __forceinline__ void unpack2(u64 x, float& a, float& b) {
    asm("mov.b64 {%0,%1}, %2;" : "=f"(a), "=f"(b) : "l"(x));
}

// ---------------- kernel 1: fold weight chains ----------------
__global__ void fuse_kernel(const float* __restrict__ Wq,  const float* __restrict__ bq,
                            const float* __restrict__ Wkv, const float* __restrict__ bkv,
                            const float* __restrict__ in_w, const float* __restrict__ in_b,
                            const float* __restrict__ out_w, const float* __restrict__ out_b,
                            const float* __restrict__ proj_w, const float* __restrict__ proj_b) {
    int tid = threadIdx.x;
    // Wq_eff[j][s] = sum_m in_w[j][m] * Wq[m][s]
    for (int idx = tid; idx < Hh*SE; idx += blockDim.x) {
        int j = idx >> 4, s = idx & 15;
        float acc = 0.f;
        for (int m = 0; m < Hh; m++) acc += in_w[j*Hh + m] * Wq[m*SE + s];
        g_WqE[idx] = acc;
    }
    // Wk_eff, Wv_eff (64 x 20)
    for (int idx = tid; idx < Hh*AC; idx += blockDim.x) {
        int j = idx / AC, a = idx % AC;
        float k = 0.f, v = 0.f;
        for (int m = 0; m < Hh; m++) {
            k += in_w[(Hh   + j)*Hh + m] * Wkv[m*AC + a];
            v += in_w[(2*Hh + j)*Hh + m] * Wkv[(Hh + m)*AC + a];
        }
        g_WkE[idx] = k; g_WvE[idx] = v;
    }
    // biases
    for (int j = tid; j < Hh; j += blockDim.x) {
        float bqe = in_b[j], bke = in_b[Hh + j], bve = in_b[2*Hh + j];
        for (int m = 0; m < Hh; m++) {
            bqe += in_w[j*Hh + m]        * bq[m];
            bke += in_w[(Hh + j)*Hh + m] * bkv[m];
            bve += in_w[(2*Hh + j)*Hh + m] * bkv[Hh + m];
        }
        g_bqE[j] = bqe; g_bkE[j] = bke; g_bvE[j] = bve;
    }
    // Wop[c][j] = sum_m proj_w[c][m] * out_w[m][j]
    for (int idx = tid; idx < AC*Hh; idx += blockDim.x) {
        int c = idx >> 6, j = idx & 63;
        float acc = 0.f;
        for (int m = 0; m < Hh; m++) acc += proj_w[c*Hh + m] * out_w[m*Hh + j];
        g_Wop[idx] = acc;
    }
    for (int c = tid; c < AC; c += blockDim.x) {
        float acc = proj_b[c];
        for (int m = 0; m < Hh; m++) acc += proj_w[c*Hh + m] * out_b[m];
        g_bop[c] = acc;
    }
}

// ---------------- kernel 2: fused QKV projection ----------------
// one warp per (b,t) row; lane computes outputs j=lane and j=lane+32
__global__ void qkv_kernel(const float* __restrict__ sem, const float* __restrict__ ac) {
    int warp = threadIdx.x >> 5, lane = threadIdx.x & 31;
    int row  = blockIdx.x * 8 + warp;            // b*T + t
    int b = row >> 10, t = row & 1023;

    float sv = (lane < SE) ? sem[(size_t)row*SE + lane] : 0.f;
    float av = (lane < AC) ? ac[(size_t)row*AC + lane]  : 0.f;

    float q0 = g_bqE[lane], q1 = g_bqE[lane + 32];
#pragma unroll
    for (int s = 0; s < SE; s++) {
        float x = __shfl_sync(0xffffffffu, sv, s);
        q0 += x * g_WqE[lane*SE + s];
        q1 += x * g_WqE[(lane + 32)*SE + s];
    }
    float k0 = g_bkE[lane], k1 = g_bkE[lane + 32];
    float v0 = g_bvE[lane], v1 = g_bvE[lane + 32];
#pragma unroll
    for (int a = 0; a < AC; a++) {
        float x = __shfl_sync(0xffffffffu, av, a);
        k0 += x * g_WkE[lane*AC + a];
        k1 += x * g_WkE[(lane + 32)*AC + a];
        v0 += x * g_WvE[lane*AC + a];
        v1 += x * g_WvE[(lane + 32)*AC + a];
    }
    // store [b][h][t][d]
    {
        int j = lane, h = j >> 4, d = j & 15;
        size_t o = (((size_t)(b*NH + h))*Tt + t)*HD + d;
        g_Q[o] = q0 * 0.25f; g_K[o] = k0; g_V[o] = v0;
    }
    {
        int j = lane + 32, h = j >> 4, d = j & 15;
        size_t o = (((size_t)(b*NH + h))*Tt + t)*HD + d;
        g_Q[o] = q1 * 0.25f; g_K[o] = k1; g_V[o] = v1;
    }
}

// ---------------- kernel 3: attention (fp32, packed f32x2 FMA) ----------------
// grid (T/256, NH, B); 128 threads, 2 queries per thread; key tiles of 128 in smem
__global__ __launch_bounds__(128) void attn_kernel() {
    int b = blockIdx.z, h = blockIdx.y;
    int q0 = blockIdx.x * 256;
    size_t base = ((size_t)(b*NH + h)) * Tt * HD;
    const float* Qb = g_Q + base;
    const float* Kb = g_K + base;
    const float* Vb = g_V + base;
    int tid = threadIdx.x;
    int qa = q0 + tid, qb = q0 + 128 + tid;

    u64 qA[8], qB[8], aA[8], aB[8];
    const u64* qpA = (const u64*)(Qb + (size_t)qa * HD);
    const u64* qpB = (const u64*)(Qb + (size_t)qb * HD);
#pragma unroll
    for (int i = 0; i < 8; i++) { qA[i] = qpA[i]; qB[i] = qpB[i]; aA[i] = 0ull; aB[i] = 0ull; }
    float lA = 0.f, lB = 0.f;

    __shared__ float sK[128*HD], sV[128*HD];

    for (int k0 = 0; k0 < Tt; k0 += 128) {
        const float4* Ks = (const float4*)(Kb + (size_t)k0 * HD);
        const float4* Vs = (const float4*)(Vb + (size_t)k0 * HD);
        float4* dK = (float4*)sK;
        float4* dV = (float4*)sV;
#pragma unroll
        for (int i = 0; i < 4; i++) {
            dK[tid + i*128] = Ks[tid + i*128];
            dV[tid + i*128] = Vs[tid + i*128];
        }
        __syncthreads();
#pragma unroll 2
        for (int k = 0; k < 128; k++) {
            const u64* kk = (const u64*)(sK + k*HD);
            const u64* vv = (const u64*)(sV + k*HD);
            u64 sA = 0ull, sB = 0ull;
#pragma unroll
            for (int i = 0; i < 8; i++) { sA = fma2(qA[i], kk[i], sA); sB = fma2(qB[i], kk[i], sB); }
            float ax, ay, bx, by;
            unpack2(sA, ax, ay); unpack2(sB, bx, by);
            float pa = __expf(ax + ay);
            float pb = __expf(bx + by);
            lA += pa; lB += pb;
            u64 pa2 = pack2(pa, pa), pb2 = pack2(pb, pb);
#pragma unroll
            for (int i = 0; i < 8; i++) { aA[i] = fma2(pa2, vv[i], aA[i]); aB[i] = fma2(pb2, vv[i], aB[i]); }
        }
        __syncthreads();
    }

    float iA = 1.f / lA, iB = 1.f / lB;
    float* dA = g_ctx + ((size_t)(b*Tt + qa))*Hh + h*HD;
    float* dB = g_ctx + ((size_t)(b*Tt + qb))*Hh + h*HD;
#pragma unroll
    for (int i = 0; i < 8; i++) {
        float x, y;
        unpack2(aA[i], x, y); dA[2*i] = x*iA; dA[2*i+1] = y*iA;
        unpack2(aB[i], x, y); dB[2*i] = x*iB; dB[2*i+1] = y*iB;
    }
}

// ---------------- kernel 4: out/proj epilogue + residual + channel stats ----------------
// 256 blocks x 256 threads; warp handles 16 rows; deterministic block reduction
__global__ void epi_kernel(const float* __restrict__ ac, const float* __restrict__ rlogit) {
    int warp = threadIdx.x >> 5, lane = threadIdx.x & 31;
    float sig = 1.f / (1.f + __expf(-rlogit[0]));

    __shared__ float sWop[AC*Hh];
    __shared__ float sbop[AC];
    for (int i = threadIdx.x; i < AC*Hh; i += blockDim.x) sWop[i] = g_Wop[i];
    if (threadIdx.x < AC) sbop[threadIdx.x] = g_bop[threadIdx.x];
    __syncthreads();

    bool act = lane < AC;
    int cc = act ? lane : 0;
    float sa = 0.f, sa2 = 0.f, se = 0.f, se2 = 0.f;

    for (int r = 0; r < 16; r++) {
        int row = blockIdx.x * 128 + warp * 16 + r;
        const float* ctx = g_ctx + (size_t)row * Hh;
        float ca = ctx[lane], cb = ctx[lane + 32];
        float e = act ? sbop[cc] : 0.f;
#pragma unroll
        for (int j = 0; j < 32; j++) {
            float x = __shfl_sync(0xffffffffu, ca, j);
            e += x * sWop[cc*Hh + j];
        }
#pragma unroll
        for (int j = 0; j < 32; j++) {
            float x = __shfl_sync(0xffffffffu, cb, j);
            e += x * sWop[cc*Hh + 32 + j];
        }
        if (act) {
            float a = ac[(size_t)row*AC + lane];
            float enh = a + sig * e;
            g_enh[(size_t)row*AC + lane] = enh;
            sa += a; sa2 += a*a; se += enh; se2 += enh*enh;
        }
    }
    __shared__ float red[8][80];
    if (act) {
        red[warp][lane] = sa; red[warp][20 + lane] = sa2;
        red[warp][40 + lane] = se; red[warp][60 + lane] = se2;
    }
    __syncthreads();
    if (threadIdx.x < 80) {
        float s = 0.f;
#pragma unroll
        for (int w = 0; w < 8; w++) s += red[w][threadIdx.x];
        g_part[blockIdx.x*80 + threadIdx.x] = s;
    }
}

// ---------------- kernel 5: finalize channel stats (deterministic) ----------------
__global__ void fin_kernel() {
    int i = threadIdx.x;
    __shared__ float S[80];
    if (i < 80) {
        float s = 0.f;
        for (int blk = 0; blk < 256; blk++) s += g_part[blk*80 + i];
        S[i] = s;
    }
    __syncthreads();
    if (i < AC) {
        const float N = (float)NROWS;
        float sa = S[i], sa2 = S[20 + i], se = S[40 + i], se2 = S[60 + i];
        float mean_a = sa / N;
        float var_a = (sa2 - sa*sa / N) / (N - 1.f);
        float std_a = sqrtf(fmaxf(var_a, 0.f));
        float orig_std = std_a + 1e-8f;
        float var_e = (se2 - se*se / N) / (N - 1.f);
        float std_e = sqrtf(fmaxf(var_e, 0.f));
        float ratio = (std_e / orig_std) / (std_a / orig_std + 1e-8f);
        float corr = (ratio < 0.4f) ? (0.4f / ratio) : 1.f;
        g_mean[i] = mean_a;
        g_corr[i] = corr;
    }
}

// ---------------- kernel 6: std correction + per-row LayerNorm ----------------
__global__ void ln_kernel(const float* __restrict__ gamma, const float* __restrict__ beta,
                          float* __restrict__ out) {
    __shared__ float sm[AC], sc[AC], sg[AC], sb[AC];
    if (threadIdx.x < AC) {
        sm[threadIdx.x] = g_mean[threadIdx.x];
        sc[threadIdx.x] = g_corr[threadIdx.x];
        sg[threadIdx.x] = gamma[threadIdx.x];
        sb[threadIdx.x] = beta[threadIdx.x];
    }
    __syncthreads();
    int row = blockIdx.x * blockDim.x + threadIdx.x;
    const float* e = g_enh + (size_t)row * AC;
    float f[AC];
    float mu = 0.f;
#pragma unroll
    for (int c = 0; c < AC; c++) {
        float x = (e[c] - sm[c]) * sc[c] + sm[c];
        f[c] = x; mu += x;
    }
    mu *= (1.f / AC);
    float var = 0.f;
#pragma unroll
    for (int c = 0; c < AC; c++) { float d = f[c] - mu; var += d*d; }
    var *= (1.f / AC);
    float r = rsqrtf(var + 1e-5f);
    float* o = out + (size_t)row * AC;
#pragma unroll
    for (int c = 0; c < AC; c++) o[c] = (f[c] - mu) * r * sg[c] + sb[c];
}

// ---------------- launch ----------------
extern "C" void kernel_launch(void* const* d_in, const int* in_sizes, int n_in,
                              void* d_out, int out_size) {
    const float* acoustic = (const float*)d_in[0];
    const float* semantic = (const float*)d_in[1];
    const float* Wq   = (const float*)d_in[2];
    const float* bq   = (const float*)d_in[3];
    const float* Wkv  = (const float*)d_in[4];
    const float* bkv  = (const float*)d_in[5];
    const float* in_w = (const float*)d_in[6];
    const float* in_b = (const float*)d_in[7];
    const float* out_w = (const float*)d_in[8];
    const float* out_b = (const float*)d_in[9];
    const float* proj_w = (const float*)d_in[10];
    const float* proj_b = (const float*)d_in[11];
    const float* rlogit = (const float*)d_in[12];
    const float* gamma = (const float*)d_in[13];
    const float* beta  = (const float*)d_in[14];
    float* out = (float*)d_out;

    fuse_kernel<<<1, 256>>>(Wq, bq, Wkv, bkv, in_w, in_b, out_w, out_b, proj_w, proj_b);
    qkv_kernel<<<NROWS/8, 256>>>(semantic, acoustic);
    attn_kernel<<<dim3(Tt/256, NH, Bb), 128>>>();
    epi_kernel<<<256, 256>>>(acoustic, rlogit);
    fin_kernel<<<1, 128>>>();
    ln_kernel<<<NROWS/256, 256>>>(gamma, beta, out);
}

// round 11
// speedup vs baseline: 2.2844x; 2.2844x over previous
#include <cuda_runtime.h>
#include <cuda_bf16.h>
#include <cstdint>

// Problem constants
#define Bb 32
#define Tt 1024
#define AC 20
#define SE 16
#define Hh 64
#define NH 4
#define HD 16
#define NROWS (Bb*Tt)   // 32768
#define EPIBLKS 512

typedef unsigned long long u64;
typedef unsigned int u32;

// ---------------- scratch (device globals; no allocation allowed) ----------------
__device__ __nv_bfloat16 g_Qh[Bb*NH*Tt*HD];  // [b][h][t][d], prescaled by 0.25*log2e
__device__ __nv_bfloat16 g_Kh[Bb*NH*Tt*HD];
__device__ __nv_bfloat16 g_Vh[Bb*NH*Tt*HD];
__device__ float g_ctx[NROWS*Hh];            // [b*T+t][64]
__device__ float g_enh[NROWS*AC];
__device__ float g_part[EPIBLKS*80];
__device__ float g_mean[AC], g_corr[AC];
// fused weights
__device__ float g_WqE[Hh*SE], g_bqE[Hh];
__device__ float g_WkE[Hh*AC], g_bkE[Hh];
__device__ float g_WvE[Hh*AC], g_bvE[Hh];
__device__ float g_Wop[AC*Hh], g_bop[AC];

// ---------------- helpers ----------------
__device__ __forceinline__ u64 fma2(u64 a, u64 b, u64 c) {
    u64 d;
    asm("fma.rn.f32x2 %0, %1, %2, %3;" : "=l"(d) : "l"(a), "l"(b), "l"(c));
    return d;
}
__device__ __forceinline__ u64 pack2(float lo, float hi) {
    u64 r; asm("mov.b64 %0, {%1,%2};" : "=l"(r) : "f"(lo), "f"(hi)); return r;
}
__device__ __forceinline__ void unpack2(u64 x, float& a, float& b) {
    asm("mov.b64 {%0,%1}, %2;" : "=f"(a), "=f"(b) : "l"(x));
}
__device__ __forceinline__ float ex2f(float x) {
    float y; asm("ex2.approx.f32 %0, %1;" : "=f"(y) : "f"(x)); return y;
}
__device__ __forceinline__ u32 cvtbf2(float hi, float lo) {
    u32 r; asm("cvt.rn.bf16x2.f32 %0, %1, %2;" : "=r"(r) : "f"(hi), "f"(lo)); return r;
}
__device__ __forceinline__ u32 smem_u32(const void* p) {
    return (u32)__cvta_generic_to_shared(p);
}
__device__ __forceinline__ void mma_bf16(
    float& d0, float& d1, float& d2, float& d3,
    u32 a0, u32 a1, u32 a2, u32 a3, u32 b0, u32 b1,
    float c0, float c1, float c2, float c3)
{
    asm volatile(
        "mma.sync.aligned.m16n8k16.row.col.f32.bf16.bf16.f32 "
        "{%0,%1,%2,%3},{%4,%5,%6,%7},{%8,%9},{%10,%11,%12,%13};"
        : "=f"(d0), "=f"(d1), "=f"(d2), "=f"(d3)
        : "r"(a0), "r"(a1), "r"(a2), "r"(a3), "r"(b0), "r"(b1),
          "f"(c0), "f"(c1), "f"(c2), "f"(c3));
}
__device__ __forceinline__ void ldsm4(u32& r0, u32& r1, u32& r2, u32& r3, u32 addr) {
    asm volatile("ldmatrix.sync.aligned.m8n8.x4.shared.b16 {%0,%1,%2,%3},[%4];"
                 : "=r"(r0), "=r"(r1), "=r"(r2), "=r"(r3) : "r"(addr));
}
__device__ __forceinline__ void ldsm4t(u32& r0, u32& r1, u32& r2, u32& r3, u32 addr) {
    asm volatile("ldmatrix.sync.aligned.m8n8.x4.trans.shared.b16 {%0,%1,%2,%3},[%4];"
                 : "=r"(r0), "=r"(r1), "=r"(r2), "=r"(r3) : "r"(addr));
}

// ---------------- kernel 1: fold weight chains ----------------
__global__ __launch_bounds__(256) void fuse_kernel(
                            const float* __restrict__ Wq,  const float* __restrict__ bq,
                            const float* __restrict__ Wkv, const float* __restrict__ bkv,
                            const float* __restrict__ in_w, const float* __restrict__ in_b,
                            const float* __restrict__ out_w, const float* __restrict__ out_b,
                            const float* __restrict__ proj_w, const float* __restrict__ proj_b) {
    int tid = threadIdx.x;
    for (int idx = tid; idx < Hh*SE; idx += blockDim.x) {
        int j = idx >> 4, s = idx & 15;
        float acc = 0.f;
        for (int m = 0; m < Hh; m++) acc += in_w[j*Hh + m] * Wq[m*SE + s];
        g_WqE[idx] = acc;
    }
    for (int idx = tid; idx < Hh*AC; idx += blockDim.x) {
        int j = idx / AC, a = idx % AC;
        float k = 0.f, v = 0.f;
        for (int m = 0; m < Hh; m++) {
            k += in_w[(Hh   + j)*Hh + m] * Wkv[m*AC + a];
            v += in_w[(2*Hh + j)*Hh + m] * Wkv[(Hh + m)*AC + a];
        }
        g_WkE[idx] = k; g_WvE[idx] = v;
    }
    for (int j = tid; j < Hh; j += blockDim.x) {
        float bqe = in_b[j], bke = in_b[Hh + j], bve = in_b[2*Hh + j];
        for (int m = 0; m < Hh; m++) {
            bqe += in_w[j*Hh + m]        * bq[m];
            bke += in_w[(Hh + j)*Hh + m] * bkv[m];
            bve += in_w[(2*Hh + j)*Hh + m] * bkv[Hh + m];
        }
        g_bqE[j] = bqe; g_bkE[j] = bke; g_bvE[j] = bve;
    }
    for (int idx = tid; idx < AC*Hh; idx += blockDim.x) {
        int c = idx >> 6, j = idx & 63;
        float acc = 0.f;
        for (int m = 0; m < Hh; m++) acc += proj_w[c*Hh + m] * out_w[m*Hh + j];
        g_Wop[idx] = acc;
    }
    for (int c = tid; c < AC; c += blockDim.x) {
        float acc = proj_b[c];
        for (int m = 0; m < Hh; m++) acc += proj_w[c*Hh + m] * out_b[m];
        g_bop[c] = acc;
    }
}

// ---------------- kernel 2: fused QKV projection -> bf16 ----------------
__global__ __launch_bounds__(256) void qkv_kernel(const float* __restrict__ sem,
                                                  const float* __restrict__ ac) {
    __shared__ float ssem[32*16];
    __shared__ float sac[32*20];
    int tid = threadIdx.x;
    int row0 = blockIdx.x * 32;

    if (tid < 128) ((float4*)ssem)[tid] = ((const float4*)(sem + (size_t)row0*SE))[tid];
    if (tid < 160) ((float4*)sac)[tid]  = ((const float4*)(ac  + (size_t)row0*AC))[tid];

    int j = tid & 63, rg = tid >> 6;
    u64 wq2[8], wk2[10], wv2[10];
#pragma unroll
    for (int s = 0; s < 8; s++) wq2[s] = pack2(g_WqE[j*16 + 2*s], g_WqE[j*16 + 2*s + 1]);
#pragma unroll
    for (int a = 0; a < 10; a++) {
        wk2[a] = pack2(g_WkE[j*20 + 2*a], g_WkE[j*20 + 2*a + 1]);
        wv2[a] = pack2(g_WvE[j*20 + 2*a], g_WvE[j*20 + 2*a + 1]);
    }
    float bq_ = g_bqE[j], bk_ = g_bkE[j], bv_ = g_bvE[j];
    const float QS = 0.25f * 1.44269504088896341f;  // 1/sqrt(HD) * log2(e)
    int h = j >> 4, d = j & 15;
    __syncthreads();

    const u64* ssem2 = (const u64*)ssem;
    const u64* sac2  = (const u64*)sac;
    for (int r = rg; r < 32; r += 4) {
        int row = row0 + r; int b = row >> 10, t = row & 1023;
        u64 q2 = 0ull, k2 = 0ull, v2 = 0ull;
#pragma unroll
        for (int s = 0; s < 8; s++) q2 = fma2(ssem2[r*8 + s], wq2[s], q2);
#pragma unroll
        for (int a = 0; a < 10; a++) {
            u64 x = sac2[r*10 + a];
            k2 = fma2(x, wk2[a], k2);
            v2 = fma2(x, wv2[a], v2);
        }
        float qx, qy, kx, ky, vx, vy;
        unpack2(q2, qx, qy); unpack2(k2, kx, ky); unpack2(v2, vx, vy);
        float q = qx + qy + bq_;
        float k = kx + ky + bk_;
        float v = vx + vy + bv_;
        size_t o = (((size_t)(b*NH + h))*Tt + t)*HD + d;
        g_Qh[o] = __float2bfloat16(q * QS);
        g_Kh[o] = __float2bfloat16(k);
        g_Vh[o] = __float2bfloat16(v);
    }
}

// ---------------- kernel 3: attention with mma.sync (bf16) ----------------
// grid (T/64, NH, B); 4 warps, each warp owns 16 q rows; key tiles of 128
__global__ __launch_bounds__(128) void attn_kernel() {
    int b = blockIdx.z, h = blockIdx.y;
    int tid = threadIdx.x;
    int warp = tid >> 5, lane = tid & 31;
    size_t base = ((size_t)(b*NH + h)) * Tt * HD;
    const __nv_bfloat16* Qg = g_Qh + base;
    const __nv_bfloat16* Kg = g_Kh + base;
    const __nv_bfloat16* Vg = g_Vh + base;

    __shared__ __nv_bfloat16 Ks[128*16];
    __shared__ __nv_bfloat16 Vs[128*16];

    int g = lane >> 2, tg = lane & 3;
    int qrow = blockIdx.x*64 + warp*16 + g;

    u32 a0 = *(const u32*)(Qg + (size_t)qrow*HD       + 2*tg);
    u32 a1 = *(const u32*)(Qg + (size_t)(qrow+8)*HD   + 2*tg);
    u32 a2 = *(const u32*)(Qg + (size_t)qrow*HD       + 2*tg + 8);
    u32 a3 = *(const u32*)(Qg + (size_t)(qrow+8)*HD   + 2*tg + 8);

    float l0 = 0.f, l1 = 0.f;
    float o00=0,o01=0,o02=0,o03=0, o10=0,o11=0,o12=0,o13=0;

    int lrow = lane & 7, lkh = (lane >> 3) & 1, ldb = lane >> 4;
    u32 koff = (u32)(((lkh*8 + lrow)*16 + ldb*8) * 2);
    u32 kbase = smem_u32(Ks) + koff;
    u32 vbase = smem_u32(Vs) + koff;

    for (int k0 = 0; k0 < Tt; k0 += 128) {
        {
            const float4* ksrc = (const float4*)(Kg + (size_t)k0*HD);
            const float4* vsrc = (const float4*)(Vg + (size_t)k0*HD);
            float4* kdst = (float4*)Ks;
            float4* vdst = (float4*)Vs;
            kdst[tid] = ksrc[tid]; kdst[tid+128] = ksrc[tid+128];
            vdst[tid] = vsrc[tid]; vdst[tid+128] = vsrc[tid+128];
        }
        __syncthreads();
#pragma unroll
        for (int c = 0; c < 8; c++) {
            u32 off = (u32)(c * 16 * 32);  // 16 keys * 32 bytes/key
            u32 kb0, kb1, kb2, kb3;
            ldsm4(kb0, kb1, kb2, kb3, kbase + off);
            float s00,s01,s02,s03, s10,s11,s12,s13;
            mma_bf16(s00,s01,s02,s03, a0,a1,a2,a3, kb0,kb2, 0.f,0.f,0.f,0.f);
            mma_bf16(s10,s11,s12,s13, a0,a1,a2,a3, kb1,kb3, 0.f,0.f,0.f,0.f);
            s00 = ex2f(s00); s01 = ex2f(s01); s02 = ex2f(s02); s03 = ex2f(s03);
            s10 = ex2f(s10); s11 = ex2f(s11); s12 = ex2f(s12); s13 = ex2f(s13);
            l0 += (s00 + s01) + (s10 + s11);
            l1 += (s02 + s03) + (s12 + s13);
            u32 p0 = cvtbf2(s01, s00);
            u32 p1 = cvtbf2(s03, s02);
            u32 p2 = cvtbf2(s11, s10);
            u32 p3 = cvtbf2(s13, s12);
            u32 vb0, vb1, vb2, vb3;
            ldsm4t(vb0, vb1, vb2, vb3, vbase + off);
            mma_bf16(o00,o01,o02,o03, p0,p1,p2,p3, vb0,vb1, o00,o01,o02,o03);
            mma_bf16(o10,o11,o12,o13, p0,p1,p2,p3, vb2,vb3, o10,o11,o12,o13);
        }
        __syncthreads();
    }

    l0 += __shfl_xor_sync(0xffffffffu, l0, 1);
    l0 += __shfl_xor_sync(0xffffffffu, l0, 2);
    l1 += __shfl_xor_sync(0xffffffffu, l1, 1);
    l1 += __shfl_xor_sync(0xffffffffu, l1, 2);
    float i0 = 1.f / l0, i1 = 1.f / l1;

    float* dst0 = g_ctx + ((size_t)(b*Tt + qrow))*Hh + h*HD + 2*tg;
    dst0[0] = o00*i0; dst0[1] = o01*i0;
    dst0[8] = o10*i0; dst0[9] = o11*i0;
    float* dst1 = g_ctx + ((size_t)(b*Tt + qrow + 8))*Hh + h*HD + 2*tg;
    dst1[0] = o02*i1; dst1[1] = o03*i1;
    dst1[8] = o12*i1; dst1[9] = o13*i1;
}

// ---------------- kernel 4: out/proj epilogue + residual + channel stats ----------------
__global__ __launch_bounds__(256) void epi_kernel(const float* __restrict__ ac,
                                                  const float* __restrict__ rlogit) {
    __shared__ float ctx_s[64*64];
    __shared__ u64 sWop2[20*33];
    __shared__ float sbop_s[AC];
    __shared__ float red[8][80];
    int tid = threadIdx.x;
    int row0 = blockIdx.x * 64;

    {
        const float4* src = (const float4*)(g_ctx + (size_t)row0*Hh);
        float4* dst = (float4*)ctx_s;
#pragma unroll
        for (int i = 0; i < 4; i++) dst[tid + i*256] = src[tid + i*256];
    }
    // FIX: grid-stride over all 640 weight pairs (was: if(tid<640) with 256 threads,
    // leaving channels 8..19 reading uninitialized smem — the 4e-3 bug)
    for (int i = tid; i < 20*32; i += 256) {
        int c = i >> 5, j2 = i & 31;
        sWop2[c*33 + j2] = pack2(g_Wop[c*64 + 2*j2], g_Wop[c*64 + 2*j2 + 1]);
    }
    if (tid < AC) sbop_s[tid] = g_bop[tid];
    __syncthreads();

    float sig = 1.f / (1.f + __expf(-rlogit[0]));
    int w8 = tid >> 5, lane = tid & 31;
    bool act = lane < AC;
    int c = act ? lane : 0;
    const u64* ctx2 = (const u64*)ctx_s;

    u64 acc[8];
#pragma unroll
    for (int r = 0; r < 8; r++) acc[r] = 0ull;
#pragma unroll 4
    for (int j2 = 0; j2 < 32; j2++) {
        u64 w = sWop2[c*33 + j2];
#pragma unroll
        for (int r = 0; r < 8; r++)
            acc[r] = fma2(ctx2[(w8*8 + r)*32 + j2], w, acc[r]);
    }

    float sa = 0.f, sa2 = 0.f, se = 0.f, se2 = 0.f;
#pragma unroll
    for (int r = 0; r < 8; r++) {
        float lo, hi; unpack2(acc[r], lo, hi);
        float e = lo + hi + sbop_s[c];
        int row = row0 + w8*8 + r;
        if (act) {
            float a = ac[(size_t)row*AC + c];
            float enh = a + sig * e;
            g_enh[(size_t)row*AC + c] = enh;
            sa += a; sa2 += a*a; se += enh; se2 += enh*enh;
        }
    }
    if (act) {
        red[w8][c] = sa; red[w8][20 + c] = sa2;
        red[w8][40 + c] = se; red[w8][60 + c] = se2;
    }
    __syncthreads();
    if (tid < 80) {
        float s = 0.f;
#pragma unroll
        for (int w = 0; w < 8; w++) s += red[w][tid];
        g_part[blockIdx.x*80 + tid] = s;
    }
}

// ---------------- kernel 5: finalize channel stats (deterministic) ----------------
__global__ __launch_bounds__(128) void fin_kernel() {
    int i = threadIdx.x;
    __shared__ float S[80];
    if (i < 80) {
        float s0 = 0.f, s1 = 0.f, s2 = 0.f, s3 = 0.f;
        for (int blk = 0; blk < EPIBLKS; blk += 4) {
            s0 += g_part[(blk+0)*80 + i];
            s1 += g_part[(blk+1)*80 + i];
            s2 += g_part[(blk+2)*80 + i];
            s3 += g_part[(blk+3)*80 + i];
        }
        S[i] = (s0 + s1) + (s2 + s3);
    }
    __syncthreads();
    if (i < AC) {
        const float N = (float)NROWS;
        float sa = S[i], sa2 = S[20 + i], se = S[40 + i], se2 = S[60 + i];
        float mean_a = sa / N;
        float var_a = (sa2 - sa*sa / N) / (N - 1.f);
        float std_a = sqrtf(fmaxf(var_a, 0.f));
        float orig_std = std_a + 1e-8f;
        float var_e = (se2 - se*se / N) / (N - 1.f);
        float std_e = sqrtf(fmaxf(var_e, 0.f));
        float ratio = (std_e / orig_std) / (std_a / orig_std + 1e-8f);
        float corr = (ratio < 0.4f) ? (0.4f / ratio) : 1.f;
        g_mean[i] = mean_a;
        g_corr[i] = corr;
    }
}

// ---------------- kernel 6: std correction + per-row LayerNorm ----------------
__global__ __launch_bounds__(256) void ln_kernel(const float* __restrict__ gamma,
                                                 const float* __restrict__ beta,
                                                 float* __restrict__ out) {
    __shared__ float sm[AC], sc[AC], sg[AC], sb[AC];
    if (threadIdx.x < AC) {
        sm[threadIdx.x] = g_mean[threadIdx.x];
        sc[threadIdx.x] = g_corr[threadIdx.x];
        sg[threadIdx.x] = gamma[threadIdx.x];
        sb[threadIdx.x] = beta[threadIdx.x];
    }
    __syncthreads();
    int row = blockIdx.x * blockDim.x + threadIdx.x;
    const float4* e4 = (const float4*)(g_enh + (size_t)row*AC);
    float4 v[5];
#pragma unroll
    for (int i = 0; i < 5; i++) v[i] = e4[i];
    const float* e = (const float*)v;
    float f[AC];
    float mu = 0.f;
#pragma unroll
    for (int c = 0; c < AC; c++) {
        float x = (e[c] - sm[c]) * sc[c] + sm[c];
        f[c] = x; mu += x;
    }
    mu *= (1.f / AC);
    float var = 0.f;
#pragma unroll
    for (int c = 0; c < AC; c++) { float d = f[c] - mu; var += d*d; }
    var *= (1.f / AC);
    float r = rsqrtf(var + 1e-5f);
    float4 w[5];
    float* o = (float*)w;
#pragma unroll
    for (int c = 0; c < AC; c++) o[c] = (f[c] - mu) * r * sg[c] + sb[c];
    float4* o4 = (float4*)(out + (size_t)row*AC);
#pragma unroll
    for (int i = 0; i < 5; i++) o4[i] = w[i];
}

// ---------------- launch ----------------
extern "C" void kernel_launch(void* const* d_in, const int* in_sizes, int n_in,
                              void* d_out, int out_size) {
    const float* acoustic = (const float*)d_in[0];
    const float* semantic = (const float*)d_in[1];
    const float* Wq   = (const float*)d_in[2];
    const float* bq   = (const float*)d_in[3];
    const float* Wkv  = (const float*)d_in[4];
    const float* bkv  = (const float*)d_in[5];
    const float* in_w = (const float*)d_in[6];
    const float* in_b = (const float*)d_in[7];
    const float* out_w = (const float*)d_in[8];
    const float* out_b = (const float*)d_in[9];
    const float* proj_w = (const float*)d_in[10];
    const float* proj_b = (const float*)d_in[11];
    const float* rlogit = (const float*)d_in[12];
    const float* gamma = (const float*)d_in[13];
    const float* beta  = (const float*)d_in[14];
    float* out = (float*)d_out;

    fuse_kernel<<<1, 256>>>(Wq, bq, Wkv, bkv, in_w, in_b, out_w, out_b, proj_w, proj_b);
    qkv_kernel<<<NROWS/32, 256>>>(semantic, acoustic);
    attn_kernel<<<dim3(Tt/64, NH, Bb), 128>>>();
    epi_kernel<<<EPIBLKS, 256>>>(acoustic, rlogit);
    fin_kernel<<<1, 128>>>();
    ln_kernel<<<NROWS/256, 256>>>(gamma, beta, out);
}

// round 12
// speedup vs baseline: 3.6862x; 1.6137x over previous
#include <cuda_runtime.h>
#include <cuda_bf16.h>
#include <cuda_fp16.h>
#include <cstdint>

// Problem constants
#define Bb 32
#define Tt 1024
#define AC 20
#define SE 16
#define Hh 64
#define NH 4
#define HD 16
#define NROWS (Bb*Tt)   // 32768
#define EPIBLKS 512

typedef unsigned long long u64;
typedef unsigned int u32;

// ---------------- scratch (device globals; no allocation allowed) ----------------
__device__ __nv_bfloat16 g_Qh[Bb*NH*Tt*HD];  // [b][h][t][d], prescaled by 0.25*log2e
__device__ __nv_bfloat16 g_Kh[Bb*NH*Tt*HD];
__device__ __half        g_Vv[Bb*NH*Tt*HD];  // f16 V
__device__ float g_ctx[NROWS*Hh];            // [b*T+t][64]
__device__ float g_enh[NROWS*AC];
__device__ float g_part[EPIBLKS*80];
__device__ float g_mean[AC], g_corr[AC];
// fused weights
__device__ float g_WqE[Hh*SE], g_bqE[Hh];
__device__ float g_WkE[Hh*AC], g_bkE[Hh];
__device__ float g_WvE[Hh*AC], g_bvE[Hh];
__device__ float g_Wop[AC*Hh], g_bop[AC];

// ---------------- helpers ----------------
__device__ __forceinline__ u64 fma2(u64 a, u64 b, u64 c) {
    u64 d;
    asm("fma.rn.f32x2 %0, %1, %2, %3;" : "=l"(d) : "l"(a), "l"(b), "l"(c));
    return d;
}
__device__ __forceinline__ u64 pack2(float lo, float hi) {
    u64 r; asm("mov.b64 %0, {%1,%2};" : "=l"(r) : "f"(lo), "f"(hi)); return r;
}
__device__ __forceinline__ void unpack2(u64 x, float& a, float& b) {
    asm("mov.b64 {%0,%1}, %2;" : "=f"(a), "=f"(b) : "l"(x));
}
__device__ __forceinline__ u32 cvtf16x2(float hi, float lo) {
    u32 r; asm("cvt.rn.f16x2.f32 %0, %1, %2;" : "=r"(r) : "f"(hi), "f"(lo)); return r;
}
__device__ __forceinline__ u32 ex2h2(u32 x) {
    u32 y; asm("ex2.approx.f16x2 %0, %1;" : "=r"(y) : "r"(x)); return y;
}
__device__ __forceinline__ u32 smem_u32(const void* p) {
    return (u32)__cvta_generic_to_shared(p);
}
__device__ __forceinline__ void mma_bf16(
    float& d0, float& d1, float& d2, float& d3,
    u32 a0, u32 a1, u32 a2, u32 a3, u32 b0, u32 b1,
    float c0, float c1, float c2, float c3)
{
    asm volatile(
        "mma.sync.aligned.m16n8k16.row.col.f32.bf16.bf16.f32 "
        "{%0,%1,%2,%3},{%4,%5,%6,%7},{%8,%9},{%10,%11,%12,%13};"
        : "=f"(d0), "=f"(d1), "=f"(d2), "=f"(d3)
        : "r"(a0), "r"(a1), "r"(a2), "r"(a3), "r"(b0), "r"(b1),
          "f"(c0), "f"(c1), "f"(c2), "f"(c3));
}
__device__ __forceinline__ void mma_f16(
    float& d0, float& d1, float& d2, float& d3,
    u32 a0, u32 a1, u32 a2, u32 a3, u32 b0, u32 b1,
    float c0, float c1, float c2, float c3)
{
    asm volatile(
        "mma.sync.aligned.m16n8k16.row.col.f32.f16.f16.f32 "
        "{%0,%1,%2,%3},{%4,%5,%6,%7},{%8,%9},{%10,%11,%12,%13};"
        : "=f"(d0), "=f"(d1), "=f"(d2), "=f"(d3)
        : "r"(a0), "r"(a1), "r"(a2), "r"(a3), "r"(b0), "r"(b1),
          "f"(c0), "f"(c1), "f"(c2), "f"(c3));
}
__device__ __forceinline__ void ldsm4(u32& r0, u32& r1, u32& r2, u32& r3, u32 addr) {
    asm volatile("ldmatrix.sync.aligned.m8n8.x4.shared.b16 {%0,%1,%2,%3},[%4];"
                 : "=r"(r0), "=r"(r1), "=r"(r2), "=r"(r3) : "r"(addr));
}
__device__ __forceinline__ void ldsm4t(u32& r0, u32& r1, u32& r2, u32& r3, u32 addr) {
    asm volatile("ldmatrix.sync.aligned.m8n8.x4.trans.shared.b16 {%0,%1,%2,%3},[%4];"
                 : "=r"(r0), "=r"(r1), "=r"(r2), "=r"(r3) : "r"(addr));
}

// ---------------- kernel 1: fold weight chains ----------------
__global__ __launch_bounds__(256) void fuse_kernel(
                            const float* __restrict__ Wq,  const float* __restrict__ bq,
                            const float* __restrict__ Wkv, const float* __restrict__ bkv,
                            const float* __restrict__ in_w, const float* __restrict__ in_b,
                            const float* __restrict__ out_w, const float* __restrict__ out_b,
                            const float* __restrict__ proj_w, const float* __restrict__ proj_b) {
    int tid = threadIdx.x;
    for (int idx = tid; idx < Hh*SE; idx += blockDim.x) {
        int j = idx >> 4, s = idx & 15;
        float acc = 0.f;
        for (int m = 0; m < Hh; m++) acc += in_w[j*Hh + m] * Wq[m*SE + s];
        g_WqE[idx] = acc;
    }
    for (int idx = tid; idx < Hh*AC; idx += blockDim.x) {
        int j = idx / AC, a = idx % AC;
        float k = 0.f, v = 0.f;
        for (int m = 0; m < Hh; m++) {
            k += in_w[(Hh   + j)*Hh + m] * Wkv[m*AC + a];
            v += in_w[(2*Hh + j)*Hh + m] * Wkv[(Hh + m)*AC + a];
        }
        g_WkE[idx] = k; g_WvE[idx] = v;
    }
    for (int j = tid; j < Hh; j += blockDim.x) {
        float bqe = in_b[j], bke = in_b[Hh + j], bve = in_b[2*Hh + j];
        for (int m = 0; m < Hh; m++) {
            bqe += in_w[j*Hh + m]        * bq[m];
            bke += in_w[(Hh + j)*Hh + m] * bkv[m];
            bve += in_w[(2*Hh + j)*Hh + m] * bkv[Hh + m];
        }
        g_bqE[j] = bqe; g_bkE[j] = bke; g_bvE[j] = bve;
    }
    for (int idx = tid; idx < AC*Hh; idx += blockDim.x) {
        int c = idx >> 6, j = idx & 63;
        float acc = 0.f;
        for (int m = 0; m < Hh; m++) acc += proj_w[c*Hh + m] * out_w[m*Hh + j];
        g_Wop[idx] = acc;
    }
    for (int c = tid; c < AC; c += blockDim.x) {
        float acc = proj_b[c];
        for (int m = 0; m < Hh; m++) acc += proj_w[c*Hh + m] * out_b[m];
        g_bop[c] = acc;
    }
}

// ---------------- kernel 2: fused QKV projection -> Q,K bf16; V f16 ----------------
// 256 blocks x 256 threads; 128 rows per block (amortize weight preload 4x)
__global__ __launch_bounds__(256) void qkv_kernel(const float* __restrict__ sem,
                                                  const float* __restrict__ ac) {
    __shared__ float ssem[128*16];
    __shared__ float sac[128*20];
    int tid = threadIdx.x;
    int row0 = blockIdx.x * 128;

    for (int i = tid; i < 512; i += 256)
        ((float4*)ssem)[i] = ((const float4*)(sem + (size_t)row0*SE))[i];
    for (int i = tid; i < 640; i += 256)
        ((float4*)sac)[i]  = ((const float4*)(ac  + (size_t)row0*AC))[i];

    int j = tid & 63, rg = tid >> 6;
    u64 wq2[8], wk2[10], wv2[10];
#pragma unroll
    for (int s = 0; s < 8; s++) wq2[s] = pack2(g_WqE[j*16 + 2*s], g_WqE[j*16 + 2*s + 1]);
#pragma unroll
    for (int a = 0; a < 10; a++) {
        wk2[a] = pack2(g_WkE[j*20 + 2*a], g_WkE[j*20 + 2*a + 1]);
        wv2[a] = pack2(g_WvE[j*20 + 2*a], g_WvE[j*20 + 2*a + 1]);
    }
    float bq_ = g_bqE[j], bk_ = g_bkE[j], bv_ = g_bvE[j];
    const float QS = 0.25f * 1.44269504088896341f;  // 1/sqrt(HD) * log2(e)
    int h = j >> 4, d = j & 15;
    __syncthreads();

    const u64* ssem2 = (const u64*)ssem;
    const u64* sac2  = (const u64*)sac;
    for (int r = rg; r < 128; r += 4) {
        int row = row0 + r; int b = row >> 10, t = row & 1023;
        u64 q2 = 0ull, k2 = 0ull, v2 = 0ull;
#pragma unroll
        for (int s = 0; s < 8; s++) q2 = fma2(ssem2[r*8 + s], wq2[s], q2);
#pragma unroll
        for (int a = 0; a < 10; a++) {
            u64 x = sac2[r*10 + a];
            k2 = fma2(x, wk2[a], k2);
            v2 = fma2(x, wv2[a], v2);
        }
        float qx, qy, kx, ky, vx, vy;
        unpack2(q2, qx, qy); unpack2(k2, kx, ky); unpack2(v2, vx, vy);
        float q = qx + qy + bq_;
        float k = kx + ky + bk_;
        float v = vx + vy + bv_;
        size_t o = (((size_t)(b*NH + h))*Tt + t)*HD + d;
        g_Qh[o] = __float2bfloat16(q * QS);
        g_Kh[o] = __float2bfloat16(k);
        g_Vv[o] = __float2half(v);
    }
}

// ---------------- kernel 3: attention — bf16 QK mma, f16x2 ex2 softmax, f16 PV mma ----
// grid (T/128, NH, B); 8 warps, each warp owns 16 q rows; key tiles of 128
__global__ __launch_bounds__(256) void attn_kernel() {
    int b = blockIdx.z, h = blockIdx.y;
    int tid = threadIdx.x;
    int warp = tid >> 5, lane = tid & 31;
    size_t base = ((size_t)(b*NH + h)) * Tt * HD;
    const __nv_bfloat16* Qg = g_Qh + base;
    const __nv_bfloat16* Kg = g_Kh + base;
    const __half* Vg = g_Vv + base;

    __shared__ __nv_bfloat16 Ks[128*16];   // 4KB
    __shared__ __half Vs[128*16];          // 4KB

    int g = lane >> 2, tg = lane & 3;
    int qrow = blockIdx.x*128 + warp*16 + g;

    u32 a0 = *(const u32*)(Qg + (size_t)qrow*HD       + 2*tg);
    u32 a1 = *(const u32*)(Qg + (size_t)(qrow+8)*HD   + 2*tg);
    u32 a2 = *(const u32*)(Qg + (size_t)qrow*HD       + 2*tg + 8);
    u32 a3 = *(const u32*)(Qg + (size_t)(qrow+8)*HD   + 2*tg + 8);

    float l0 = 0.f, l1 = 0.f;
    float o00=0,o01=0,o02=0,o03=0, o10=0,o11=0,o12=0,o13=0;

    int lrow = lane & 7, lkh = (lane >> 3) & 1, ldb = lane >> 4;
    u32 koff = (u32)(((lkh*8 + lrow)*16 + ldb*8) * 2);
    u32 kbase = smem_u32(Ks) + koff;
    u32 vbase = smem_u32(Vs) + koff;

    for (int k0 = 0; k0 < Tt; k0 += 128) {
        {
            const float4* ksrc = (const float4*)(Kg + (size_t)k0*HD);
            const float4* vsrc = (const float4*)(Vg + (size_t)k0*HD);
            ((float4*)Ks)[tid] = ksrc[tid];
            ((float4*)Vs)[tid] = vsrc[tid];
        }
        __syncthreads();
#pragma unroll
        for (int c = 0; c < 8; c++) {
            u32 off = (u32)(c * 16 * 32);  // 16 keys * 32 bytes/key
            u32 kb0, kb1, kb2, kb3;
            ldsm4(kb0, kb1, kb2, kb3, kbase + off);
            float s00,s01,s02,s03, s10,s11,s12,s13;
            mma_bf16(s00,s01,s02,s03, a0,a1,a2,a3, kb0,kb2, 0.f,0.f,0.f,0.f);
            mma_bf16(s10,s11,s12,s13, a0,a1,a2,a3, kb1,kb3, 0.f,0.f,0.f,0.f);
            // pack scores to f16x2 (same hi/lo convention as validated bf16 path)
            u32 p0 = cvtf16x2(s01, s00);   // row g,   keys 2tg..  (dtile low)
            u32 p1 = cvtf16x2(s03, s02);   // row g+8
            u32 p2 = cvtf16x2(s11, s10);   // row g,   keys +8
            u32 p3 = cvtf16x2(s13, s12);   // row g+8
            // exp2 in half2: 2 exps per MUFU op
            p0 = ex2h2(p0); p1 = ex2h2(p1); p2 = ex2h2(p2); p3 = ex2h2(p3);
            // l accumulation (fp32)
            {
                __half2 t02 = __hadd2(*(__half2*)&p0, *(__half2*)&p2);
                __half2 t13 = __hadd2(*(__half2*)&p1, *(__half2*)&p3);
                float2 f02 = __half22float2(t02);
                float2 f13 = __half22float2(t13);
                l0 += f02.x + f02.y;
                l1 += f13.x + f13.y;
            }
            u32 vb0, vb1, vb2, vb3;
            ldsm4t(vb0, vb1, vb2, vb3, vbase + off);
            mma_f16(o00,o01,o02,o03, p0,p1,p2,p3, vb0,vb1, o00,o01,o02,o03);
            mma_f16(o10,o11,o12,o13, p0,p1,p2,p3, vb2,vb3, o10,o11,o12,o13);
        }
        __syncthreads();
    }

    l0 += __shfl_xor_sync(0xffffffffu, l0, 1);
    l0 += __shfl_xor_sync(0xffffffffu, l0, 2);
    l1 += __shfl_xor_sync(0xffffffffu, l1, 1);
    l1 += __shfl_xor_sync(0xffffffffu, l1, 2);
    float i0 = 1.f / l0, i1 = 1.f / l1;

    float* dst0 = g_ctx + ((size_t)(b*Tt + qrow))*Hh + h*HD + 2*tg;
    dst0[0] = o00*i0; dst0[1] = o01*i0;
    dst0[8] = o10*i0; dst0[9] = o11*i0;
    float* dst1 = g_ctx + ((size_t)(b*Tt + qrow + 8))*Hh + h*HD + 2*tg;
    dst1[0] = o02*i1; dst1[1] = o03*i1;
    dst1[8] = o12*i1; dst1[9] = o13*i1;
}

// ---------------- kernel 4: out/proj epilogue + residual + channel stats ----------------
__global__ __launch_bounds__(256) void epi_kernel(const float* __restrict__ ac,
                                                  const float* __restrict__ rlogit) {
    __shared__ float ctx_s[64*64];
    __shared__ u64 sWop2[20*33];
    __shared__ float sbop_s[AC];
    __shared__ float red[8][80];
    int tid = threadIdx.x;
    int row0 = blockIdx.x * 64;

    {
        const float4* src = (const float4*)(g_ctx + (size_t)row0*Hh);
        float4* dst = (float4*)ctx_s;
#pragma unroll
        for (int i = 0; i < 4; i++) dst[tid + i*256] = src[tid + i*256];
    }
    for (int i = tid; i < 20*32; i += 256) {
        int c = i >> 5, j2 = i & 31;
        sWop2[c*33 + j2] = pack2(g_Wop[c*64 + 2*j2], g_Wop[c*64 + 2*j2 + 1]);
    }
    if (tid < AC) sbop_s[tid] = g_bop[tid];
    __syncthreads();

    float sig = 1.f / (1.f + __expf(-rlogit[0]));
    int w8 = tid >> 5, lane = tid & 31;
    bool act = lane < AC;
    int c = act ? lane : 0;
    const u64* ctx2 = (const u64*)ctx_s;

    u64 acc[8];
#pragma unroll
    for (int r = 0; r < 8; r++) acc[r] = 0ull;
#pragma unroll 4
    for (int j2 = 0; j2 < 32; j2++) {
        u64 w = sWop2[c*33 + j2];
#pragma unroll
        for (int r = 0; r < 8; r++)
            acc[r] = fma2(ctx2[(w8*8 + r)*32 + j2], w, acc[r]);
    }

    float sa = 0.f, sa2 = 0.f, se = 0.f, se2 = 0.f;
#pragma unroll
    for (int r = 0; r < 8; r++) {
        float lo, hi; unpack2(acc[r], lo, hi);
        float e = lo + hi + sbop_s[c];
        int row = row0 + w8*8 + r;
        if (act) {
            float a = ac[(size_t)row*AC + c];
            float enh = a + sig * e;
            g_enh[(size_t)row*AC + c] = enh;
            sa += a; sa2 += a*a; se += enh; se2 += enh*enh;
        }
    }
    if (act) {
        red[w8][c] = sa; red[w8][20 + c] = sa2;
        red[w8][40 + c] = se; red[w8][60 + c] = se2;
    }
    __syncthreads();
    if (tid < 80) {
        float s = 0.f;
#pragma unroll
        for (int w = 0; w < 8; w++) s += red[w][tid];
        g_part[blockIdx.x*80 + tid] = s;
    }
}

// ---------------- kernel 5: finalize channel stats (parallel, deterministic) --------
__global__ __launch_bounds__(320) void fin_kernel() {
    int tid = threadIdx.x;
    __shared__ float part4[4][80];
    __shared__ float S[80];
    {
        int chunk = tid / 80, col = tid - chunk*80;   // tid < 320 always
        float s0 = 0.f, s1 = 0.f, s2 = 0.f, s3 = 0.f;
        int base = chunk * 128;
        for (int blk = 0; blk < 128; blk += 4) {
            s0 += g_part[(base+blk+0)*80 + col];
            s1 += g_part[(base+blk+1)*80 + col];
            s2 += g_part[(base+blk+2)*80 + col];
            s3 += g_part[(base+blk+3)*80 + col];
        }
        part4[chunk][col] = (s0 + s1) + (s2 + s3);
    }
    __syncthreads();
    if (tid < 80)
        S[tid] = (part4[0][tid] + part4[1][tid]) + (part4[2][tid] + part4[3][tid]);
    __syncthreads();
    if (tid < AC) {
        int i = tid;
        const float N = (float)NROWS;
        float sa = S[i], sa2 = S[20 + i], se = S[40 + i], se2 = S[60 + i];
        float mean_a = sa / N;
        float var_a = (sa2 - sa*sa / N) / (N - 1.f);
        float std_a = sqrtf(fmaxf(var_a, 0.f));
        float orig_std = std_a + 1e-8f;
        float var_e = (se2 - se*se / N) / (N - 1.f);
        float std_e = sqrtf(fmaxf(var_e, 0.f));
        float ratio = (std_e / orig_std) / (std_a / orig_std + 1e-8f);
        float corr = (ratio < 0.4f) ? (0.4f / ratio) : 1.f;
        g_mean[i] = mean_a;
        g_corr[i] = corr;
    }
}

// ---------------- kernel 6: std correction + per-row LayerNorm ----------------
__global__ __launch_bounds__(256) void ln_kernel(const float* __restrict__ gamma,
                                                 const float* __restrict__ beta,
                                                 float* __restrict__ out) {
    __shared__ float sm[AC], sc[AC], sg[AC], sb[AC];
    if (threadIdx.x < AC) {
        sm[threadIdx.x] = g_mean[threadIdx.x];
        sc[threadIdx.x] = g_corr[threadIdx.x];
        sg[threadIdx.x] = gamma[threadIdx.x];
        sb[threadIdx.x] = beta[threadIdx.x];
    }
    __syncthreads();
    int row = blockIdx.x * blockDim.x + threadIdx.x;
    const float4* e4 = (const float4*)(g_enh + (size_t)row*AC);
    float4 v[5];
#pragma unroll
    for (int i = 0; i < 5; i++) v[i] = e4[i];
    const float* e = (const float*)v;
    float f[AC];
    float mu = 0.f;
#pragma unroll
    for (int c = 0; c < AC; c++) {
        float x = (e[c] - sm[c]) * sc[c] + sm[c];
        f[c] = x; mu += x;
    }
    mu *= (1.f / AC);
    float var = 0.f;
#pragma unroll
    for (int c = 0; c < AC; c++) { float d = f[c] - mu; var += d*d; }
    var *= (1.f / AC);
    float r = rsqrtf(var + 1e-5f);
    float4 w[5];
    float* o = (float*)w;
#pragma unroll
    for (int c = 0; c < AC; c++) o[c] = (f[c] - mu) * r * sg[c] + sb[c];
    float4* o4 = (float4*)(out + (size_t)row*AC);
#pragma unroll
    for (int i = 0; i < 5; i++) o4[i] = w[i];
}

// ---------------- launch ----------------
extern "C" void kernel_launch(void* const* d_in, const int* in_sizes, int n_in,
                              void* d_out, int out_size) {
    const float* acoustic = (const float*)d_in[0];
    const float* semantic = (const float*)d_in[1];
    const float* Wq   = (const float*)d_in[2];
    const float* bq   = (const float*)d_in[3];
    const float* Wkv  = (const float*)d_in[4];
    const float* bkv  = (const float*)d_in[5];
    const float* in_w = (const float*)d_in[6];
    const float* in_b = (const float*)d_in[7];
    const float* out_w = (const float*)d_in[8];
    const float* out_b = (const float*)d_in[9];
    const float* proj_w = (const float*)d_in[10];
    const float* proj_b = (const float*)d_in[11];
    const float* rlogit = (const float*)d_in[12];
    const float* gamma = (const float*)d_in[13];
    const float* beta  = (const float*)d_in[14];
    float* out = (float*)d_out;

    fuse_kernel<<<1, 256>>>(Wq, bq, Wkv, bkv, in_w, in_b, out_w, out_b, proj_w, proj_b);
    qkv_kernel<<<NROWS/128, 256>>>(semantic, acoustic);
    attn_kernel<<<dim3(Tt/128, NH, Bb), 256>>>();
    epi_kernel<<<EPIBLKS, 256>>>(acoustic, rlogit);
    fin_kernel<<<1, 320>>>();
    ln_kernel<<<NROWS/256, 256>>>(gamma, beta, out);
}

// round 13
// speedup vs baseline: 3.9673x; 1.0763x over previous
#include <cuda_runtime.h>
#include <cuda_bf16.h>
#include <cuda_fp16.h>
#include <cstdint>

// Problem constants
#define Bb 32
#define Tt 1024
#define AC 20
#define SE 16
#define Hh 64
#define NH 4
#define HD 16
#define NROWS (Bb*Tt)   // 32768
#define EPIBLKS 1024

typedef unsigned long long u64;
typedef unsigned int u32;

// ---------------- scratch (device globals; no allocation allowed) ----------------
__device__ __nv_bfloat16 g_Qh[Bb*NH*Tt*HD];  // [b][h][t][d], prescaled by 0.25*log2e
__device__ __nv_bfloat16 g_Kh[Bb*NH*Tt*HD];
__device__ __half        g_Vv[Bb*NH*Tt*HD];  // f16 V
__device__ float g_ctx[NROWS*Hh];            // [b*T+t][64]
__device__ float g_enh[NROWS*AC];
__device__ float g_part[EPIBLKS*80];
__device__ float g_mean[AC], g_corr[AC];
// fused weights
__device__ float g_WqE[Hh*SE], g_bqE[Hh];
__device__ float g_WkE[Hh*AC], g_bkE[Hh];
__device__ float g_WvE[Hh*AC], g_bvE[Hh];
__device__ float g_Wop[AC*Hh], g_bop[AC];

// ---------------- helpers ----------------
__device__ __forceinline__ u64 fma2(u64 a, u64 b, u64 c) {
    u64 d;
    asm("fma.rn.f32x2 %0, %1, %2, %3;" : "=l"(d) : "l"(a), "l"(b), "l"(c));
    return d;
}
__device__ __forceinline__ u64 pack2(float lo, float hi) {
    u64 r; asm("mov.b64 %0, {%1,%2};" : "=l"(r) : "f"(lo), "f"(hi)); return r;
}
__device__ __forceinline__ void unpack2(u64 x, float& a, float& b) {
    asm("mov.b64 {%0,%1}, %2;" : "=f"(a), "=f"(b) : "l"(x));
}
__device__ __forceinline__ u32 cvtf16x2(float hi, float lo) {
    u32 r; asm("cvt.rn.f16x2.f32 %0, %1, %2;" : "=r"(r) : "f"(hi), "f"(lo)); return r;
}
__device__ __forceinline__ u32 ex2h2(u32 x) {
    u32 y; asm("ex2.approx.f16x2 %0, %1;" : "=r"(y) : "r"(x)); return y;
}
__device__ __forceinline__ u32 smem_u32(const void* p) {
    return (u32)__cvta_generic_to_shared(p);
}
__device__ __forceinline__ void mma_bf16(
    float& d0, float& d1, float& d2, float& d3,
    u32 a0, u32 a1, u32 a2, u32 a3, u32 b0, u32 b1,
    float c0, float c1, float c2, float c3)
{
    asm volatile(
        "mma.sync.aligned.m16n8k16.row.col.f32.bf16.bf16.f32 "
        "{%0,%1,%2,%3},{%4,%5,%6,%7},{%8,%9},{%10,%11,%12,%13};"
        : "=f"(d0), "=f"(d1), "=f"(d2), "=f"(d3)
        : "r"(a0), "r"(a1), "r"(a2), "r"(a3), "r"(b0), "r"(b1),
          "f"(c0), "f"(c1), "f"(c2), "f"(c3));
}
__device__ __forceinline__ void mma_f16(
    float& d0, float& d1, float& d2, float& d3,
    u32 a0, u32 a1, u32 a2, u32 a3, u32 b0, u32 b1,
    float c0, float c1, float c2, float c3)
{
    asm volatile(
        "mma.sync.aligned.m16n8k16.row.col.f32.f16.f16.f32 "
        "{%0,%1,%2,%3},{%4,%5,%6,%7},{%8,%9},{%10,%11,%12,%13};"
        : "=f"(d0), "=f"(d1), "=f"(d2), "=f"(d3)
        : "r"(a0), "r"(a1), "r"(a2), "r"(a3), "r"(b0), "r"(b1),
          "f"(c0), "f"(c1), "f"(c2), "f"(c3));
}
__device__ __forceinline__ void ldsm4(u32& r0, u32& r1, u32& r2, u32& r3, u32 addr) {
    asm volatile("ldmatrix.sync.aligned.m8n8.x4.shared.b16 {%0,%1,%2,%3},[%4];"
                 : "=r"(r0), "=r"(r1), "=r"(r2), "=r"(r3) : "r"(addr));
}
__device__ __forceinline__ void ldsm4t(u32& r0, u32& r1, u32& r2, u32& r3, u32 addr) {
    asm volatile("ldmatrix.sync.aligned.m8n8.x4.trans.shared.b16 {%0,%1,%2,%3},[%4];"
                 : "=r"(r0), "=r"(r1), "=r"(r2), "=r"(r3) : "r"(addr));
}

// ---------------- kernel 1: fold weight chains (parallel, grid-stride) ----------------
__global__ __launch_bounds__(256) void fuse_kernel(
                            const float* __restrict__ Wq,  const float* __restrict__ bq,
                            const float* __restrict__ Wkv, const float* __restrict__ bkv,
                            const float* __restrict__ in_w, const float* __restrict__ in_b,
                            const float* __restrict__ out_w, const float* __restrict__ out_b,
                            const float* __restrict__ proj_w, const float* __restrict__ proj_b) {
    int tid0 = blockIdx.x * blockDim.x + threadIdx.x;
    int gs = blockDim.x * gridDim.x;
    for (int idx = tid0; idx < Hh*SE; idx += gs) {
        int j = idx >> 4, s = idx & 15;
        float acc = 0.f;
        for (int m = 0; m < Hh; m++) acc += in_w[j*Hh + m] * Wq[m*SE + s];
        g_WqE[idx] = acc;
    }
    for (int idx = tid0; idx < Hh*AC; idx += gs) {
        int j = idx / AC, a = idx % AC;
        float k = 0.f, v = 0.f;
        for (int m = 0; m < Hh; m++) {
            k += in_w[(Hh   + j)*Hh + m] * Wkv[m*AC + a];
            v += in_w[(2*Hh + j)*Hh + m] * Wkv[(Hh + m)*AC + a];
        }
        g_WkE[idx] = k; g_WvE[idx] = v;
    }
    for (int j = tid0; j < Hh; j += gs) {
        float bqe = in_b[j], bke = in_b[Hh + j], bve = in_b[2*Hh + j];
        for (int m = 0; m < Hh; m++) {
            bqe += in_w[j*Hh + m]        * bq[m];
            bke += in_w[(Hh + j)*Hh + m] * bkv[m];
            bve += in_w[(2*Hh + j)*Hh + m] * bkv[Hh + m];
        }
        g_bqE[j] = bqe; g_bkE[j] = bke; g_bvE[j] = bve;
    }
    for (int idx = tid0; idx < AC*Hh; idx += gs) {
        int c = idx >> 6, j = idx & 63;
        float acc = 0.f;
        for (int m = 0; m < Hh; m++) acc += proj_w[c*Hh + m] * out_w[m*Hh + j];
        g_Wop[idx] = acc;
    }
    for (int c = tid0; c < AC; c += gs) {
        float acc = proj_b[c];
        for (int m = 0; m < Hh; m++) acc += proj_w[c*Hh + m] * out_b[m];
        g_bop[c] = acc;
    }
}

// ---------------- kernel 2: fused QKV projection -> Q,K bf16; V f16 ----------------
// 256 blocks x 256 threads; 128 rows per block (amortize weight preload 4x)
__global__ __launch_bounds__(256) void qkv_kernel(const float* __restrict__ sem,
                                                  const float* __restrict__ ac) {
    __shared__ float ssem[128*16];
    __shared__ float sac[128*20];
    int tid = threadIdx.x;
    int row0 = blockIdx.x * 128;

    for (int i = tid; i < 512; i += 256)
        ((float4*)ssem)[i] = ((const float4*)(sem + (size_t)row0*SE))[i];
    for (int i = tid; i < 640; i += 256)
        ((float4*)sac)[i]  = ((const float4*)(ac  + (size_t)row0*AC))[i];

    int j = tid & 63, rg = tid >> 6;
    u64 wq2[8], wk2[10], wv2[10];
#pragma unroll
    for (int s = 0; s < 8; s++) wq2[s] = pack2(g_WqE[j*16 + 2*s], g_WqE[j*16 + 2*s + 1]);
#pragma unroll
    for (int a = 0; a < 10; a++) {
        wk2[a] = pack2(g_WkE[j*20 + 2*a], g_WkE[j*20 + 2*a + 1]);
        wv2[a] = pack2(g_WvE[j*20 + 2*a], g_WvE[j*20 + 2*a + 1]);
    }
    float bq_ = g_bqE[j], bk_ = g_bkE[j], bv_ = g_bvE[j];
    const float QS = 0.25f * 1.44269504088896341f;  // 1/sqrt(HD) * log2(e)
    int h = j >> 4, d = j & 15;
    __syncthreads();

    const u64* ssem2 = (const u64*)ssem;
    const u64* sac2  = (const u64*)sac;
    for (int r = rg; r < 128; r += 4) {
        int row = row0 + r; int b = row >> 10, t = row & 1023;
        u64 q2 = 0ull, k2 = 0ull, v2 = 0ull;
#pragma unroll
        for (int s = 0; s < 8; s++) q2 = fma2(ssem2[r*8 + s], wq2[s], q2);
#pragma unroll
        for (int a = 0; a < 10; a++) {
            u64 x = sac2[r*10 + a];
            k2 = fma2(x, wk2[a], k2);
            v2 = fma2(x, wv2[a], v2);
        }
        float qx, qy, kx, ky, vx, vy;
        unpack2(q2, qx, qy); unpack2(k2, kx, ky); unpack2(v2, vx, vy);
        float q = qx + qy + bq_;
        float k = kx + ky + bk_;
        float v = vx + vy + bv_;
        size_t o = (((size_t)(b*NH + h))*Tt + t)*HD + d;
        g_Qh[o] = __float2bfloat16(q * QS);
        g_Kh[o] = __float2bfloat16(k);
        g_Vv[o] = __float2half(v);
    }
}

// ---------------- kernel 3: attention — bf16 QK mma, f16x2 ex2 softmax, f16 PV mma ----
// grid (T/128, NH, B); 8 warps, each warp owns 16 q rows; key tiles of 128
__global__ __launch_bounds__(256) void attn_kernel() {
    int b = blockIdx.z, h = blockIdx.y;
    int tid = threadIdx.x;
    int warp = tid >> 5, lane = tid & 31;
    size_t base = ((size_t)(b*NH + h)) * Tt * HD;
    const __nv_bfloat16* Qg = g_Qh + base;
    const __nv_bfloat16* Kg = g_Kh + base;
    const __half* Vg = g_Vv + base;

    __shared__ __nv_bfloat16 Ks[128*16];   // 4KB
    __shared__ __half Vs[128*16];          // 4KB

    int g = lane >> 2, tg = lane & 3;
    int qrow = blockIdx.x*128 + warp*16 + g;

    u32 a0 = *(const u32*)(Qg + (size_t)qrow*HD       + 2*tg);
    u32 a1 = *(const u32*)(Qg + (size_t)(qrow+8)*HD   + 2*tg);
    u32 a2 = *(const u32*)(Qg + (size_t)qrow*HD       + 2*tg + 8);
    u32 a3 = *(const u32*)(Qg + (size_t)(qrow+8)*HD   + 2*tg + 8);

    float l0 = 0.f, l1 = 0.f;
    float o00=0,o01=0,o02=0,o03=0, o10=0,o11=0,o12=0,o13=0;

    int lrow = lane & 7, lkh = (lane >> 3) & 1, ldb = lane >> 4;
    u32 koff = (u32)(((lkh*8 + lrow)*16 + ldb*8) * 2);
    u32 kbase = smem_u32(Ks) + koff;
    u32 vbase = smem_u32(Vs) + koff;

    for (int k0 = 0; k0 < Tt; k0 += 128) {
        {
            const float4* ksrc = (const float4*)(Kg + (size_t)k0*HD);
            const float4* vsrc = (const float4*)(Vg + (size_t)k0*HD);
            ((float4*)Ks)[tid] = ksrc[tid];
            ((float4*)Vs)[tid] = vsrc[tid];
        }
        __syncthreads();
#pragma unroll
        for (int c = 0; c < 8; c++) {
            u32 off = (u32)(c * 16 * 32);  // 16 keys * 32 bytes/key
            u32 kb0, kb1, kb2, kb3;
            ldsm4(kb0, kb1, kb2, kb3, kbase + off);
            float s00,s01,s02,s03, s10,s11,s12,s13;
            mma_bf16(s00,s01,s02,s03, a0,a1,a2,a3, kb0,kb2, 0.f,0.f,0.f,0.f);
            mma_bf16(s10,s11,s12,s13, a0,a1,a2,a3, kb1,kb3, 0.f,0.f,0.f,0.f);
            u32 p0 = cvtf16x2(s01, s00);
            u32 p1 = cvtf16x2(s03, s02);
            u32 p2 = cvtf16x2(s11, s10);
            u32 p3 = cvtf16x2(s13, s12);
            p0 = ex2h2(p0); p1 = ex2h2(p1); p2 = ex2h2(p2); p3 = ex2h2(p3);
            {
                __half2 t02 = __hadd2(*(__half2*)&p0, *(__half2*)&p2);
                __half2 t13 = __hadd2(*(__half2*)&p1, *(__half2*)&p3);
                float2 f02 = __half22float2(t02);
                float2 f13 = __half22float2(t13);
                l0 += f02.x + f02.y;
                l1 += f13.x + f13.y;
            }
            u32 vb0, vb1, vb2, vb3;
            ldsm4t(vb0, vb1, vb2, vb3, vbase + off);
            mma_f16(o00,o01,o02,o03, p0,p1,p2,p3, vb0,vb1, o00,o01,o02,o03);
            mma_f16(o10,o11,o12,o13, p0,p1,p2,p3, vb2,vb3, o10,o11,o12,o13);
        }
        __syncthreads();
    }

    l0 += __shfl_xor_sync(0xffffffffu, l0, 1);
    l0 += __shfl_xor_sync(0xffffffffu, l0, 2);
    l1 += __shfl_xor_sync(0xffffffffu, l1, 1);
    l1 += __shfl_xor_sync(0xffffffffu, l1, 2);
    float i0 = 1.f / l0, i1 = 1.f / l1;

    float* dst0 = g_ctx + ((size_t)(b*Tt + qrow))*Hh + h*HD + 2*tg;
    dst0[0] = o00*i0; dst0[1] = o01*i0;
    dst0[8] = o10*i0; dst0[9] = o11*i0;
    float* dst1 = g_ctx + ((size_t)(b*Tt + qrow + 8))*Hh + h*HD + 2*tg;
    dst1[0] = o02*i1; dst1[1] = o03*i1;
    dst1[8] = o12*i1; dst1[9] = o13*i1;
}

// ---------------- kernel 4: out/proj epilogue + residual + channel stats ----------------
// 1024 blocks x 256 threads; 32 rows/block; 128-bit LDS for weights and ctx
__global__ __launch_bounds__(256) void epi_kernel(const float* __restrict__ ac,
                                                  const float* __restrict__ rlogit) {
    __shared__ float ctx_s[32*64];       // 8KB
    __shared__ u64 sWop2[20*34];         // pitch 34 => 16B-aligned pairs
    __shared__ float sbop_s[AC];
    __shared__ float red[8][80];
    int tid = threadIdx.x;
    int row0 = blockIdx.x * 32;

    {
        const float4* src = (const float4*)(g_ctx + (size_t)row0*Hh);
        float4* dst = (float4*)ctx_s;
        dst[tid]       = src[tid];
        dst[tid + 256] = src[tid + 256];
    }
    for (int i = tid; i < 20*32; i += 256) {
        int c = i >> 5, j2 = i & 31;
        sWop2[c*34 + j2] = pack2(g_Wop[c*64 + 2*j2], g_Wop[c*64 + 2*j2 + 1]);
    }
    if (tid < AC) sbop_s[tid] = g_bop[tid];
    __syncthreads();

    float sig = 1.f / (1.f + __expf(-rlogit[0]));
    int w8 = tid >> 5, lane = tid & 31;
    bool act = lane < AC;
    int c = act ? lane : 0;
    const u64* ctx2 = (const u64*)ctx_s;

    u64 acc[4];
#pragma unroll
    for (int r = 0; r < 4; r++) acc[r] = 0ull;
#pragma unroll
    for (int j4 = 0; j4 < 16; j4++) {
        ulonglong2 w = *(const ulonglong2*)&sWop2[c*34 + 2*j4];
#pragma unroll
        for (int r = 0; r < 4; r++) {
            ulonglong2 ct = *(const ulonglong2*)&ctx2[(w8*4 + r)*32 + 2*j4];
            acc[r] = fma2(ct.x, w.x, acc[r]);
            acc[r] = fma2(ct.y, w.y, acc[r]);
        }
    }

    float sa = 0.f, sa2 = 0.f, se = 0.f, se2 = 0.f;
#pragma unroll
    for (int r = 0; r < 4; r++) {
        float lo, hi; unpack2(acc[r], lo, hi);
        float e = lo + hi + sbop_s[c];
        int row = row0 + w8*4 + r;
        if (act) {
            float a = ac[(size_t)row*AC + c];
            float enh = a + sig * e;
            g_enh[(size_t)row*AC + c] = enh;
            sa += a; sa2 += a*a; se += enh; se2 += enh*enh;
        }
    }
    if (act) {
        red[w8][c] = sa; red[w8][20 + c] = sa2;
        red[w8][40 + c] = se; red[w8][60 + c] = se2;
    }
    __syncthreads();
    if (tid < 80) {
        float s = 0.f;
#pragma unroll
        for (int w = 0; w < 8; w++) s += red[w][tid];
        g_part[blockIdx.x*80 + tid] = s;
    }
}

// ---------------- kernel 5: finalize channel stats (parallel, deterministic) --------
__global__ __launch_bounds__(320) void fin_kernel() {
    int tid = threadIdx.x;
    __shared__ float part4[4][80];
    __shared__ float S[80];
    {
        int chunk = tid / 80, col = tid - chunk*80;   // tid < 320 always
        float s0 = 0.f, s1 = 0.f, s2 = 0.f, s3 = 0.f;
        int base = chunk * (EPIBLKS/4);
        for (int blk = 0; blk < EPIBLKS/4; blk += 4) {
            s0 += g_part[(base+blk+0)*80 + col];
            s1 += g_part[(base+blk+1)*80 + col];
            s2 += g_part[(base+blk+2)*80 + col];
            s3 += g_part[(base+blk+3)*80 + col];
        }
        part4[chunk][col] = (s0 + s1) + (s2 + s3);
    }
    __syncthreads();
    if (tid < 80)
        S[tid] = (part4[0][tid] + part4[1][tid]) + (part4[2][tid] + part4[3][tid]);
    __syncthreads();
    if (tid < AC) {
        int i = tid;
        const float N = (float)NROWS;
        float sa = S[i], sa2 = S[20 + i], se = S[40 + i], se2 = S[60 + i];
        float mean_a = sa / N;
        float var_a = (sa2 - sa*sa / N) / (N - 1.f);
        float std_a = sqrtf(fmaxf(var_a, 0.f));
        float orig_std = std_a + 1e-8f;
        float var_e = (se2 - se*se / N) / (N - 1.f);
        float std_e = sqrtf(fmaxf(var_e, 0.f));
        float ratio = (std_e / orig_std) / (std_a / orig_std + 1e-8f);
        float corr = (ratio < 0.4f) ? (0.4f / ratio) : 1.f;
        g_mean[i] = mean_a;
        g_corr[i] = corr;
    }
}

// ---------------- kernel 6: std correction + per-row LayerNorm ----------------
__global__ __launch_bounds__(256) void ln_kernel(const float* __restrict__ gamma,
                                                 const float* __restrict__ beta,
                                                 float* __restrict__ out) {
    __shared__ float sm[AC], sc[AC], sg[AC], sb[AC];
    if (threadIdx.x < AC) {
        sm[threadIdx.x] = g_mean[threadIdx.x];
        sc[threadIdx.x] = g_corr[threadIdx.x];
        sg[threadIdx.x] = gamma[threadIdx.x];
        sb[threadIdx.x] = beta[threadIdx.x];
    }
    __syncthreads();
    int row = blockIdx.x * blockDim.x + threadIdx.x;
    const float4* e4 = (const float4*)(g_enh + (size_t)row*AC);
    float4 v[5];
#pragma unroll
    for (int i = 0; i < 5; i++) v[i] = e4[i];
    const float* e = (const float*)v;
    float f[AC];
    float mu = 0.f;
#pragma unroll
    for (int c = 0; c < AC; c++) {
        float x = (e[c] - sm[c]) * sc[c] + sm[c];
        f[c] = x; mu += x;
    }
    mu *= (1.f / AC);
    float var = 0.f;
#pragma unroll
    for (int c = 0; c < AC; c++) { float d = f[c] - mu; var += d*d; }
    var *= (1.f / AC);
    float r = rsqrtf(var + 1e-5f);
    float4 w[5];
    float* o = (float*)w;
#pragma unroll
    for (int c = 0; c < AC; c++) o[c] = (f[c] - mu) * r * sg[c] + sb[c];
    float4* o4 = (float4*)(out + (size_t)row*AC);
#pragma unroll
    for (int i = 0; i < 5; i++) o4[i] = w[i];
}

// ---------------- launch ----------------
extern "C" void kernel_launch(void* const* d_in, const int* in_sizes, int n_in,
                              void* d_out, int out_size) {
    const float* acoustic = (const float*)d_in[0];
    const float* semantic = (const float*)d_in[1];
    const float* Wq   = (const float*)d_in[2];
    const float* bq   = (const float*)d_in[3];
    const float* Wkv  = (const float*)d_in[4];
    const float* bkv  = (const float*)d_in[5];
    const float* in_w = (const float*)d_in[6];
    const float* in_b = (const float*)d_in[7];
    const float* out_w = (const float*)d_in[8];
    const float* out_b = (const float*)d_in[9];
    const float* proj_w = (const float*)d_in[10];
    const float* proj_b = (const float*)d_in[11];
    const float* rlogit = (const float*)d_in[12];
    const float* gamma = (const float*)d_in[13];
    const float* beta  = (const float*)d_in[14];
    float* out = (float*)d_out;

    fuse_kernel<<<8, 256>>>(Wq, bq, Wkv, bkv, in_w, in_b, out_w, out_b, proj_w, proj_b);
    qkv_kernel<<<NROWS/128, 256>>>(semantic, acoustic);
    attn_kernel<<<dim3(Tt/128, NH, Bb), 256>>>();
    epi_kernel<<<EPIBLKS, 256>>>(acoustic, rlogit);
    fin_kernel<<<1, 320>>>();
    ln_kernel<<<NROWS/256, 256>>>(gamma, beta, out);
}

// round 15
// speedup vs baseline: 4.2698x; 1.0763x over previous
#include <cuda_runtime.h>
#include <cuda_bf16.h>
#include <cuda_fp16.h>
#include <cstdint>

// Problem constants
#define Bb 32
#define Tt 1024
#define AC 20
#define SE 16
#define Hh 64
#define NH 4
#define HD 16
#define NROWS (Bb*Tt)   // 32768
#define NBLK 256        // attn CTAs = (Tt/128) * Bb

typedef unsigned long long u64;
typedef unsigned int u32;

// ---------------- scratch (device globals; no allocation allowed) ----------------
__device__ __nv_bfloat16 g_Qh[Bb*NH*Tt*HD];  // [b][h][t][d], prescaled by 0.25*log2e
__device__ __nv_bfloat16 g_Kh[Bb*NH*Tt*HD];
__device__ __half        g_Vv[Bb*NH*Tt*HD];  // f16 V
__device__ float g_enh[NROWS*AC];
__device__ float g_part[NBLK*80];
__device__ float g_mean[AC], g_corr[AC];
__device__ int   g_ticket;                   // zero-init; last CTA resets
// fused weights
__device__ float g_WqE[Hh*SE], g_bqE[Hh];
__device__ float g_WkE[Hh*AC], g_bkE[Hh];
__device__ float g_WvE[Hh*AC], g_bvE[Hh];
__device__ float g_Wop[AC*Hh], g_bop[AC];

// ---------------- helpers ----------------
__device__ __forceinline__ u64 fma2(u64 a, u64 b, u64 c) {
    u64 d;
    asm("fma.rn.f32x2 %0, %1, %2, %3;" : "=l"(d) : "l"(a), "l"(b), "l"(c));
    return d;
}
__device__ __forceinline__ u64 pack2(float lo, float hi) {
    u64 r; asm("mov.b64 %0, {%1,%2};" : "=l"(r) : "f"(lo), "f"(hi)); return r;
}
__device__ __forceinline__ void unpack2(u64 x, float& a, float& b) {
    asm("mov.b64 {%0,%1}, %2;" : "=f"(a), "=f"(b) : "l"(x));
}
__device__ __forceinline__ u32 cvtf16x2(float hi, float lo) {
    u32 r; asm("cvt.rn.f16x2.f32 %0, %1, %2;" : "=r"(r) : "f"(hi), "f"(lo)); return r;
}
__device__ __forceinline__ u32 ex2h2(u32 x) {
    u32 y; asm("ex2.approx.f16x2 %0, %1;" : "=r"(y) : "r"(x)); return y;
}
__device__ __forceinline__ u32 smem_u32(const void* p) {
    return (u32)__cvta_generic_to_shared(p);
}
__device__ __forceinline__ void mma_bf16(
    float& d0, float& d1, float& d2, float& d3,
    u32 a0, u32 a1, u32 a2, u32 a3, u32 b0, u32 b1,
    float c0, float c1, float c2, float c3)
{
    asm volatile(
        "mma.sync.aligned.m16n8k16.row.col.f32.bf16.bf16.f32 "
        "{%0,%1,%2,%3},{%4,%5,%6,%7},{%8,%9},{%10,%11,%12,%13};"
        : "=f"(d0), "=f"(d1), "=f"(d2), "=f"(d3)
        : "r"(a0), "r"(a1), "r"(a2), "r"(a3), "r"(b0), "r"(b1),
          "f"(c0), "f"(c1), "f"(c2), "f"(c3));
}
__device__ __forceinline__ void mma_f16(
    float& d0, float& d1, float& d2, float& d3,
    u32 a0, u32 a1, u32 a2, u32 a3, u32 b0, u32 b1,
    float c0, float c1, float c2, float c3)
{
    asm volatile(
        "mma.sync.aligned.m16n8k16.row.col.f32.f16.f16.f32 "
        "{%0,%1,%2,%3},{%4,%5,%6,%7},{%8,%9},{%10,%11,%12,%13};"
        : "=f"(d0), "=f"(d1), "=f"(d2), "=f"(d3)
        : "r"(a0), "r"(a1), "r"(a2), "r"(a3), "r"(b0), "r"(b1),
          "f"(c0), "f"(c1), "f"(c2), "f"(c3));
}
__device__ __forceinline__ void ldsm4(u32& r0, u32& r1, u32& r2, u32& r3, u32 addr) {
    asm volatile("ldmatrix.sync.aligned.m8n8.x4.shared.b16 {%0,%1,%2,%3},[%4];"
                 : "=r"(r0), "=r"(r1), "=r"(r2), "=r"(r3) : "r"(addr));
}
__device__ __forceinline__ void ldsm4t(u32& r0, u32& r1, u32& r2, u32& r3, u32 addr) {
    asm volatile("ldmatrix.sync.aligned.m8n8.x4.trans.shared.b16 {%0,%1,%2,%3},[%4];"
                 : "=r"(r0), "=r"(r1), "=r"(r2), "=r"(r3) : "r"(addr));
}

// ---------------- kernel 1: fold weight chains (parallel, grid-stride) ----------------
__global__ __launch_bounds__(256) void fuse_kernel(
                            const float* __restrict__ Wq,  const float* __restrict__ bq,
                            const float* __restrict__ Wkv, const float* __restrict__ bkv,
                            const float* __restrict__ in_w, const float* __restrict__ in_b,
                            const float* __restrict__ out_w, const float* __restrict__ out_b,
                            const float* __restrict__ proj_w, const float* __restrict__ proj_b) {
    int tid0 = blockIdx.x * blockDim.x + threadIdx.x;
    int gs = blockDim.x * gridDim.x;
    for (int idx = tid0; idx < Hh*SE; idx += gs) {
        int j = idx >> 4, s = idx & 15;
        float acc = 0.f;
        for (int m = 0; m < Hh; m++) acc += in_w[j*Hh + m] * Wq[m*SE + s];
        g_WqE[idx] = acc;
    }
    for (int idx = tid0; idx < Hh*AC; idx += gs) {
        int j = idx / AC, a = idx % AC;
        float k = 0.f, v = 0.f;
        for (int m = 0; m < Hh; m++) {
            k += in_w[(Hh   + j)*Hh + m] * Wkv[m*AC + a];
            v += in_w[(2*Hh + j)*Hh + m] * Wkv[(Hh + m)*AC + a];
        }
        g_WkE[idx] = k; g_WvE[idx] = v;
    }
    for (int j = tid0; j < Hh; j += gs) {
        float bqe = in_b[j], bke = in_b[Hh + j], bve = in_b[2*Hh + j];
        for (int m = 0; m < Hh; m++) {
            bqe += in_w[j*Hh + m]        * bq[m];
            bke += in_w[(Hh + j)*Hh + m] * bkv[m];
            bve += in_w[(2*Hh + j)*Hh + m] * bkv[Hh + m];
        }
        g_bqE[j] = bqe; g_bkE[j] = bke; g_bvE[j] = bve;
    }
    for (int idx = tid0; idx < AC*Hh; idx += gs) {
        int c = idx >> 6, j = idx & 63;
        float acc = 0.f;
        for (int m = 0; m < Hh; m++) acc += proj_w[c*Hh + m] * out_w[m*Hh + j];
        g_Wop[idx] = acc;
    }
    for (int c = tid0; c < AC; c += gs) {
        float acc = proj_b[c];
        for (int m = 0; m < Hh; m++) acc += proj_w[c*Hh + m] * out_b[m];
        g_bop[c] = acc;
    }
}

// ---------------- kernel 2: fused QKV projection -> Q,K bf16; V f16 ----------------
__global__ __launch_bounds__(256) void qkv_kernel(const float* __restrict__ sem,
                                                  const float* __restrict__ ac) {
    __shared__ float ssem[128*16];
    __shared__ float sac[128*20];
    int tid = threadIdx.x;
    int row0 = blockIdx.x * 128;

    for (int i = tid; i < 512; i += 256)
        ((float4*)ssem)[i] = ((const float4*)(sem + (size_t)row0*SE))[i];
    for (int i = tid; i < 640; i += 256)
        ((float4*)sac)[i]  = ((const float4*)(ac  + (size_t)row0*AC))[i];

    int j = tid & 63, rg = tid >> 6;
    u64 wq2[8], wk2[10], wv2[10];
#pragma unroll
    for (int s = 0; s < 8; s++) wq2[s] = pack2(g_WqE[j*16 + 2*s], g_WqE[j*16 + 2*s + 1]);
#pragma unroll
    for (int a = 0; a < 10; a++) {
        wk2[a] = pack2(g_WkE[j*20 + 2*a], g_WkE[j*20 + 2*a + 1]);
        wv2[a] = pack2(g_WvE[j*20 + 2*a], g_WvE[j*20 + 2*a + 1]);
    }
    float bq_ = g_bqE[j], bk_ = g_bkE[j], bv_ = g_bvE[j];
    const float QS = 0.25f * 1.44269504088896341f;  // 1/sqrt(HD) * log2(e)
    int h = j >> 4, d = j & 15;
    __syncthreads();

    const u64* ssem2 = (const u64*)ssem;
    const u64* sac2  = (const u64*)sac;
    for (int r = rg; r < 128; r += 4) {
        int row = row0 + r; int b = row >> 10, t = row & 1023;
        u64 q2 = 0ull, k2 = 0ull, v2 = 0ull;
#pragma unroll
        for (int s = 0; s < 8; s++) q2 = fma2(ssem2[r*8 + s], wq2[s], q2);
#pragma unroll
        for (int a = 0; a < 10; a++) {
            u64 x = sac2[r*10 + a];
            k2 = fma2(x, wk2[a], k2);
            v2 = fma2(x, wv2[a], v2);
        }
        float qx, qy, kx, ky, vx, vy;
        unpack2(q2, qx, qy); unpack2(k2, kx, ky); unpack2(v2, vx, vy);
        float q = qx + qy + bq_;
        float k = kx + ky + bk_;
        float v = vx + vy + bv_;
        size_t o = (((size_t)(b*NH + h))*Tt + t)*HD + d;
        g_Qh[o] = __float2bfloat16(q * QS);
        g_Kh[o] = __float2bfloat16(k);
        g_Vv[o] = __float2half(v);
    }
}

// ---------------- kernel 3: FUSED attention + out/proj epilogue + stats + finalize ----
// grid (Tt/128, Bb); 8 warps; each CTA: 128 q-rows, all 4 heads; ctx stays in smem
__global__ __launch_bounds__(256) void attn_epi_kernel(const float* __restrict__ ac,
                                                       const float* __restrict__ rlogit) {
    __shared__ __align__(16) __nv_bfloat16 Ks[128*16];   // 4KB
    __shared__ __align__(16) __half Vs[128*16];          // 4KB
    __shared__ __align__(16) float ctx_s[128*64];        // 32KB
    __shared__ __align__(16) u64 sWop2[20*34];           // 5.44KB (pitch 34 -> 16B pairs)
    __shared__ float sbop_s[AC];
    __shared__ float red[8][80];                         // reused by fin
    __shared__ int s_rank;

    int b = blockIdx.y;
    int tid = threadIdx.x;
    int warp = tid >> 5, lane = tid & 31;
    int g = lane >> 2, tg = lane & 3;

    // preload epi weights (phase 2)
    for (int i = tid; i < 20*32; i += 256) {
        int c = i >> 5, j2 = i & 31;
        sWop2[c*34 + j2] = pack2(g_Wop[c*64 + 2*j2], g_Wop[c*64 + 2*j2 + 1]);
    }
    if (tid < AC) sbop_s[tid] = g_bop[tid];

    int lrow = lane & 7, lkh = (lane >> 3) & 1, ldb = lane >> 4;
    u32 koff = (u32)(((lkh*8 + lrow)*16 + ldb*8) * 2);
    u32 kbase = smem_u32(Ks) + koff;
    u32 vbase = smem_u32(Vs) + koff;

    int qrow_local = warp*16 + g;               // 0..127 (and +8)
    int qrow = blockIdx.x*128 + qrow_local;

    // ---------- phase 1: attention, 4 heads sequential ----------
#pragma unroll 1
    for (int h = 0; h < NH; h++) {
        size_t base = ((size_t)(b*NH + h)) * Tt * HD;
        const __nv_bfloat16* Qg = g_Qh + base;
        const __nv_bfloat16* Kg = g_Kh + base;
        const __half* Vg = g_Vv + base;

        u32 a0 = *(const u32*)(Qg + (size_t)qrow*HD       + 2*tg);
        u32 a1 = *(const u32*)(Qg + (size_t)(qrow+8)*HD   + 2*tg);
        u32 a2 = *(const u32*)(Qg + (size_t)qrow*HD       + 2*tg + 8);
        u32 a3 = *(const u32*)(Qg + (size_t)(qrow+8)*HD   + 2*tg + 8);

        float l0 = 0.f, l1 = 0.f;
        float o00=0,o01=0,o02=0,o03=0, o10=0,o11=0,o12=0,o13=0;

        for (int k0 = 0; k0 < Tt; k0 += 128) {
            __syncthreads();   // previous tile (or previous head's) reads done
            {
                const float4* ksrc = (const float4*)(Kg + (size_t)k0*HD);
                const float4* vsrc = (const float4*)(Vg + (size_t)k0*HD);
                ((float4*)Ks)[tid] = ksrc[tid];
                ((float4*)Vs)[tid] = vsrc[tid];
            }
            __syncthreads();
#pragma unroll
            for (int c = 0; c < 8; c++) {
                u32 off = (u32)(c * 16 * 32);
                u32 kb0, kb1, kb2, kb3;
                ldsm4(kb0, kb1, kb2, kb3, kbase + off);
                float s00,s01,s02,s03, s10,s11,s12,s13;
                mma_bf16(s00,s01,s02,s03, a0,a1,a2,a3, kb0,kb2, 0.f,0.f,0.f,0.f);
                mma_bf16(s10,s11,s12,s13, a0,a1,a2,a3, kb1,kb3, 0.f,0.f,0.f,0.f);
                u32 p0 = cvtf16x2(s01, s00);
                u32 p1 = cvtf16x2(s03, s02);
                u32 p2 = cvtf16x2(s11, s10);
                u32 p3 = cvtf16x2(s13, s12);
                p0 = ex2h2(p0); p1 = ex2h2(p1); p2 = ex2h2(p2); p3 = ex2h2(p3);
                {
                    __half2 t02 = __hadd2(*(__half2*)&p0, *(__half2*)&p2);
                    __half2 t13 = __hadd2(*(__half2*)&p1, *(__half2*)&p3);
                    float2 f02 = __half22float2(t02);
                    float2 f13 = __half22float2(t13);
                    l0 += f02.x + f02.y;
                    l1 += f13.x + f13.y;
                }
                u32 vb0, vb1, vb2, vb3;
                ldsm4t(vb0, vb1, vb2, vb3, vbase + off);
                mma_f16(o00,o01,o02,o03, p0,p1,p2,p3, vb0,vb1, o00,o01,o02,o03);
                mma_f16(o10,o11,o12,o13, p0,p1,p2,p3, vb2,vb3, o10,o11,o12,o13);
            }
        }

        l0 += __shfl_xor_sync(0xffffffffu, l0, 1);
        l0 += __shfl_xor_sync(0xffffffffu, l0, 2);
        l1 += __shfl_xor_sync(0xffffffffu, l1, 1);
        l1 += __shfl_xor_sync(0xffffffffu, l1, 2);
        float i0 = 1.f / l0, i1 = 1.f / l1;

        float* dst0 = ctx_s + qrow_local*Hh + h*HD + 2*tg;
        dst0[0] = o00*i0; dst0[1] = o01*i0;
        dst0[8] = o10*i0; dst0[9] = o11*i0;
        float* dst1 = ctx_s + (qrow_local+8)*Hh + h*HD + 2*tg;
        dst1[0] = o02*i1; dst1[1] = o03*i1;
        dst1[8] = o12*i1; dst1[9] = o13*i1;
    }
    __syncthreads();

    // ---------- phase 2: out/proj epilogue + residual + channel stats ----------
    float sig = 1.f / (1.f + __expf(-rlogit[0]));
    bool act = lane < AC;
    int c = act ? lane : 0;
    const u64* ctx2 = (const u64*)ctx_s;
    float sa = 0.f, sa2 = 0.f, se = 0.f, se2 = 0.f;

#pragma unroll 1
    for (int half = 0; half < 2; half++) {
        int rbase = warp*16 + half*8;
        u64 acc[8];
#pragma unroll
        for (int r = 0; r < 8; r++) acc[r] = 0ull;
#pragma unroll
        for (int j4 = 0; j4 < 16; j4++) {
            ulonglong2 w = *(const ulonglong2*)&sWop2[c*34 + 2*j4];
#pragma unroll
            for (int r = 0; r < 8; r++) {
                ulonglong2 ct = *(const ulonglong2*)&ctx2[(rbase + r)*32 + 2*j4];
                acc[r] = fma2(ct.x, w.x, acc[r]);
                acc[r] = fma2(ct.y, w.y, acc[r]);
            }
        }
#pragma unroll
        for (int r = 0; r < 8; r++) {
            float lo, hi; unpack2(acc[r], lo, hi);
            float e = lo + hi + sbop_s[c];
            size_t grow = (size_t)b*Tt + blockIdx.x*128 + rbase + r;
            if (act) {
                float a = ac[grow*AC + c];
                float enh = a + sig * e;
                g_enh[grow*AC + c] = enh;
                sa += a; sa2 += a*a; se += enh; se2 += enh*enh;
            }
        }
    }
    if (act) {
        red[warp][c] = sa; red[warp][20 + c] = sa2;
        red[warp][40 + c] = se; red[warp][60 + c] = se2;
    }
    __syncthreads();
    int bid = blockIdx.y*gridDim.x + blockIdx.x;   // 0..255
    if (tid < 80) {
        float s = 0.f;
#pragma unroll
        for (int w = 0; w < 8; w++) s += red[w][tid];
        g_part[bid*80 + tid] = s;
    }

    // ---------- phase 3: last CTA finalizes channel stats ----------
    __threadfence();
    __syncthreads();
    if (tid == 0) s_rank = atomicAdd(&g_ticket, 1);
    __syncthreads();
    if (s_rank == NBLK - 1) {
        __threadfence();
        if (tid < 160) {
            int chunk = tid / 80, col = tid - chunk*80;
            float s0 = 0.f, s1 = 0.f, s2 = 0.f, s3 = 0.f;
            int base2 = chunk * 128;
            for (int blk = 0; blk < 128; blk += 4) {
                s0 += g_part[(base2+blk+0)*80 + col];
                s1 += g_part[(base2+blk+1)*80 + col];
                s2 += g_part[(base2+blk+2)*80 + col];
                s3 += g_part[(base2+blk+3)*80 + col];
            }
            red[chunk][col] = (s0 + s1) + (s2 + s3);
        }
        __syncthreads();
        if (tid < 80) red[2][tid] = red[0][tid] + red[1][tid];
        __syncthreads();
        if (tid < AC) {
            int i = tid;
            const float N = (float)NROWS;
            float sa_ = red[2][i], sa2_ = red[2][20 + i];
            float se_ = red[2][40 + i], se2_ = red[2][60 + i];
            float mean_a = sa_ / N;
            float var_a = (sa2_ - sa_*sa_ / N) / (N - 1.f);
            float std_a = sqrtf(fmaxf(var_a, 0.f));
            float orig_std = std_a + 1e-8f;
            float var_e = (se2_ - se_*se_ / N) / (N - 1.f);
            float std_e = sqrtf(fmaxf(var_e, 0.f));
            float ratio = (std_e / orig_std) / (std_a / orig_std + 1e-8f);
            float corr = (ratio < 0.4f) ? (0.4f / ratio) : 1.f;
            g_mean[i] = mean_a;
            g_corr[i] = corr;
        }
        __syncthreads();
        if (tid == 0) atomicExch(&g_ticket, 0);   // reset for next replay
    }
}

// ---------------- kernel 4: std correction + per-row LayerNorm ----------------
__global__ __launch_bounds__(256) void ln_kernel(const float* __restrict__ gamma,
                                                 const float* __restrict__ beta,
                                                 float* __restrict__ out) {
    __shared__ float sm[AC], sc[AC], sg[AC], sb[AC];
    if (threadIdx.x < AC) {
        sm[threadIdx.x] = g_mean[threadIdx.x];
        sc[threadIdx.x] = g_corr[threadIdx.x];
        sg[threadIdx.x] = gamma[threadIdx.x];
        sb[threadIdx.x] = beta[threadIdx.x];
    }
    __syncthreads();
    int row = blockIdx.x * blockDim.x + threadIdx.x;
    const float4* e4 = (const float4*)(g_enh + (size_t)row*AC);
    float4 v[5];
#pragma unroll
    for (int i = 0; i < 5; i++) v[i] = e4[i];
    const float* e = (const float*)v;
    float f[AC];
    float mu = 0.f;
#pragma unroll
    for (int c = 0; c < AC; c++) {
        float x = (e[c] - sm[c]) * sc[c] + sm[c];
        f[c] = x; mu += x;
    }
    mu *= (1.f / AC);
    float var = 0.f;
#pragma unroll
    for (int c = 0; c < AC; c++) { float d = f[c] - mu; var += d*d; }
    var *= (1.f / AC);
    float r = rsqrtf(var + 1e-5f);
    float4 w[5];
    float* o = (float*)w;
#pragma unroll
    for (int c = 0; c < AC; c++) o[c] = (f[c] - mu) * r * sg[c] + sb[c];
    float4* o4 = (float4*)(out + (size_t)row*AC);
#pragma unroll
    for (int i = 0; i < 5; i++) o4[i] = w[i];
}

// ---------------- launch ----------------
extern "C" void kernel_launch(void* const* d_in, const int* in_sizes, int n_in,
                              void* d_out, int out_size) {
    const float* acoustic = (const float*)d_in[0];
    const float* semantic = (const float*)d_in[1];
    const float* Wq   = (const float*)d_in[2];
    const float* bq   = (const float*)d_in[3];
    const float* Wkv  = (const float*)d_in[4];
    const float* bkv  = (const float*)d_in[5];
    const float* in_w = (const float*)d_in[6];
    const float* in_b = (const float*)d_in[7];
    const float* out_w = (const float*)d_in[8];
    const float* out_b = (const float*)d_in[9];
    const float* proj_w = (const float*)d_in[10];
    const float* proj_b = (const float*)d_in[11];
    const float* rlogit = (const float*)d_in[12];
    const float* gamma = (const float*)d_in[13];
    const float* beta  = (const float*)d_in[14];
    float* out = (float*)d_out;

    fuse_kernel<<<8, 256>>>(Wq, bq, Wkv, bkv, in_w, in_b, out_w, out_b, proj_w, proj_b);
    qkv_kernel<<<NROWS/128, 256>>>(semantic, acoustic);
    attn_epi_kernel<<<dim3(Tt/128, Bb), 256>>>(acoustic, rlogit);
    ln_kernel<<<NROWS/256, 256>>>(gamma, beta, out);
}

// round 16
// speedup vs baseline: 4.3715x; 1.0238x over previous
#include <cuda_runtime.h>
#include <cuda_bf16.h>
#include <cuda_fp16.h>
#include <cstdint>

// Problem constants
#define Bb 32
#define Tt 1024
#define AC 20
#define SE 16
#define Hh 64
#define NH 4
#define HD 16
#define NROWS (Bb*Tt)   // 32768
#define NBLK 256        // attn CTAs = (Tt/128) * Bb

typedef unsigned long long u64;
typedef unsigned int u32;

// ---------------- scratch (device globals; no allocation allowed) ----------------
__device__ __nv_bfloat16 g_Qh[Bb*NH*Tt*HD];  // [b][h][t][d], prescaled by 0.25*log2e
__device__ __nv_bfloat16 g_Kh[Bb*NH*Tt*HD];
__device__ __half        g_Vv[Bb*NH*Tt*HD];  // f16 V
__device__ float g_enh[NROWS*AC];
__device__ float g_part[NBLK*80];
__device__ float g_mean[AC], g_corr[AC];
__device__ int   g_ticket;                   // zero-init; finalizer resets
__device__ int   g_flag;                     // stats-ready flag; last passer resets
__device__ int   g_passed;                   // ln-done counter; last passer resets
// fused weights
__device__ float g_WqE[Hh*SE], g_bqE[Hh];
__device__ float g_WkE[Hh*AC], g_bkE[Hh];
__device__ float g_WvE[Hh*AC], g_bvE[Hh];
__device__ float g_Wop[AC*Hh], g_bop[AC];

// ---------------- helpers ----------------
__device__ __forceinline__ u64 fma2(u64 a, u64 b, u64 c) {
    u64 d;
    asm("fma.rn.f32x2 %0, %1, %2, %3;" : "=l"(d) : "l"(a), "l"(b), "l"(c));
    return d;
}
__device__ __forceinline__ u64 pack2(float lo, float hi) {
    u64 r; asm("mov.b64 %0, {%1,%2};" : "=l"(r) : "f"(lo), "f"(hi)); return r;
}
__device__ __forceinline__ void unpack2(u64 x, float& a, float& b) {
    asm("mov.b64 {%0,%1}, %2;" : "=f"(a), "=f"(b) : "l"(x));
}
__device__ __forceinline__ u32 cvtf16x2(float hi, float lo) {
    u32 r; asm("cvt.rn.f16x2.f32 %0, %1, %2;" : "=r"(r) : "f"(hi), "f"(lo)); return r;
}
__device__ __forceinline__ u32 ex2h2(u32 x) {
    u32 y; asm("ex2.approx.f16x2 %0, %1;" : "=r"(y) : "r"(x)); return y;
}
__device__ __forceinline__ u32 smem_u32(const void* p) {
    return (u32)__cvta_generic_to_shared(p);
}
__device__ __forceinline__ void mma_bf16(
    float& d0, float& d1, float& d2, float& d3,
    u32 a0, u32 a1, u32 a2, u32 a3, u32 b0, u32 b1,
    float c0, float c1, float c2, float c3)
{
    asm volatile(
        "mma.sync.aligned.m16n8k16.row.col.f32.bf16.bf16.f32 "
        "{%0,%1,%2,%3},{%4,%5,%6,%7},{%8,%9},{%10,%11,%12,%13};"
        : "=f"(d0), "=f"(d1), "=f"(d2), "=f"(d3)
        : "r"(a0), "r"(a1), "r"(a2), "r"(a3), "r"(b0), "r"(b1),
          "f"(c0), "f"(c1), "f"(c2), "f"(c3));
}
__device__ __forceinline__ void mma_f16(
    float& d0, float& d1, float& d2, float& d3,
    u32 a0, u32 a1, u32 a2, u32 a3, u32 b0, u32 b1,
    float c0, float c1, float c2, float c3)
{
    asm volatile(
        "mma.sync.aligned.m16n8k16.row.col.f32.f16.f16.f32 "
        "{%0,%1,%2,%3},{%4,%5,%6,%7},{%8,%9},{%10,%11,%12,%13};"
        : "=f"(d0), "=f"(d1), "=f"(d2), "=f"(d3)
        : "r"(a0), "r"(a1), "r"(a2), "r"(a3), "r"(b0), "r"(b1),
          "f"(c0), "f"(c1), "f"(c2), "f"(c3));
}
__device__ __forceinline__ void ldsm4(u32& r0, u32& r1, u32& r2, u32& r3, u32 addr) {
    asm volatile("ldmatrix.sync.aligned.m8n8.x4.shared.b16 {%0,%1,%2,%3},[%4];"
                 : "=r"(r0), "=r"(r1), "=r"(r2), "=r"(r3) : "r"(addr));
}
__device__ __forceinline__ void ldsm4t(u32& r0, u32& r1, u32& r2, u32& r3, u32 addr) {
    asm volatile("ldmatrix.sync.aligned.m8n8.x4.trans.shared.b16 {%0,%1,%2,%3},[%4];"
                 : "=r"(r0), "=r"(r1), "=r"(r2), "=r"(r3) : "r"(addr));
}

// ---------------- kernel 1: fold weight chains (parallel, grid-stride) ----------------
__global__ __launch_bounds__(256) void fuse_kernel(
                            const float* __restrict__ Wq,  const float* __restrict__ bq,
                            const float* __restrict__ Wkv, const float* __restrict__ bkv,
                            const float* __restrict__ in_w, const float* __restrict__ in_b,
                            const float* __restrict__ out_w, const float* __restrict__ out_b,
                            const float* __restrict__ proj_w, const float* __restrict__ proj_b) {
    int tid0 = blockIdx.x * blockDim.x + threadIdx.x;
    int gs = blockDim.x * gridDim.x;
    for (int idx = tid0; idx < Hh*SE; idx += gs) {
        int j = idx >> 4, s = idx & 15;
        float acc = 0.f;
        for (int m = 0; m < Hh; m++) acc += in_w[j*Hh + m] * Wq[m*SE + s];
        g_WqE[idx] = acc;
    }
    for (int idx = tid0; idx < Hh*AC; idx += gs) {
        int j = idx / AC, a = idx % AC;
        float k = 0.f, v = 0.f;
        for (int m = 0; m < Hh; m++) {
            k += in_w[(Hh   + j)*Hh + m] * Wkv[m*AC + a];
            v += in_w[(2*Hh + j)*Hh + m] * Wkv[(Hh + m)*AC + a];
        }
        g_WkE[idx] = k; g_WvE[idx] = v;
    }
    for (int j = tid0; j < Hh; j += gs) {
        float bqe = in_b[j], bke = in_b[Hh + j], bve = in_b[2*Hh + j];
        for (int m = 0; m < Hh; m++) {
            bqe += in_w[j*Hh + m]        * bq[m];
            bke += in_w[(Hh + j)*Hh + m] * bkv[m];
            bve += in_w[(2*Hh + j)*Hh + m] * bkv[Hh + m];
        }
        g_bqE[j] = bqe; g_bkE[j] = bke; g_bvE[j] = bve;
    }
    for (int idx = tid0; idx < AC*Hh; idx += gs) {
        int c = idx >> 6, j = idx & 63;
        float acc = 0.f;
        for (int m = 0; m < Hh; m++) acc += proj_w[c*Hh + m] * out_w[m*Hh + j];
        g_Wop[idx] = acc;
    }
    for (int c = tid0; c < AC; c += gs) {
        float acc = proj_b[c];
        for (int m = 0; m < Hh; m++) acc += proj_w[c*Hh + m] * out_b[m];
        g_bop[c] = acc;
    }
}

// ---------------- kernel 2: fused QKV projection -> Q,K bf16; V f16 ----------------
__global__ __launch_bounds__(256) void qkv_kernel(const float* __restrict__ sem,
                                                  const float* __restrict__ ac) {
    __shared__ float ssem[128*16];
    __shared__ float sac[128*20];
    int tid = threadIdx.x;
    int row0 = blockIdx.x * 128;

    for (int i = tid; i < 512; i += 256)
        ((float4*)ssem)[i] = ((const float4*)(sem + (size_t)row0*SE))[i];
    for (int i = tid; i < 640; i += 256)
        ((float4*)sac)[i]  = ((const float4*)(ac  + (size_t)row0*AC))[i];

    int j = tid & 63, rg = tid >> 6;
    u64 wq2[8], wk2[10], wv2[10];
#pragma unroll
    for (int s = 0; s < 8; s++) wq2[s] = pack2(g_WqE[j*16 + 2*s], g_WqE[j*16 + 2*s + 1]);
#pragma unroll
    for (int a = 0; a < 10; a++) {
        wk2[a] = pack2(g_WkE[j*20 + 2*a], g_WkE[j*20 + 2*a + 1]);
        wv2[a] = pack2(g_WvE[j*20 + 2*a], g_WvE[j*20 + 2*a + 1]);
    }
    float bq_ = g_bqE[j], bk_ = g_bkE[j], bv_ = g_bvE[j];
    const float QS = 0.25f * 1.44269504088896341f;  // 1/sqrt(HD) * log2(e)
    int h = j >> 4, d = j & 15;
    __syncthreads();

    const u64* ssem2 = (const u64*)ssem;
    const u64* sac2  = (const u64*)sac;
    for (int r = rg; r < 128; r += 4) {
        int row = row0 + r; int b = row >> 10, t = row & 1023;
        u64 q2 = 0ull, k2 = 0ull, v2 = 0ull;
#pragma unroll
        for (int s = 0; s < 8; s++) q2 = fma2(ssem2[r*8 + s], wq2[s], q2);
#pragma unroll
        for (int a = 0; a < 10; a++) {
            u64 x = sac2[r*10 + a];
            k2 = fma2(x, wk2[a], k2);
            v2 = fma2(x, wv2[a], v2);
        }
        float qx, qy, kx, ky, vx, vy;
        unpack2(q2, qx, qy); unpack2(k2, kx, ky); unpack2(v2, vx, vy);
        float q = qx + qy + bq_;
        float k = kx + ky + bk_;
        float v = vx + vy + bv_;
        size_t o = (((size_t)(b*NH + h))*Tt + t)*HD + d;
        g_Qh[o] = __float2bfloat16(q * QS);
        g_Kh[o] = __float2bfloat16(k);
        g_Vv[o] = __float2half(v);
    }
}

// ---------------- kernel 3: FUSED attention + epilogue + stats + finalize + LN ----
// grid (Tt/128, Bb) = 256 CTAs; __launch_bounds__(256,2) => occ>=2 => capacity 296
// >= 256 CTAs all co-resident => grid-wide flag sync is deadlock-free.
__global__ __launch_bounds__(256, 2) void attn_epi_kernel(
        const float* __restrict__ ac, const float* __restrict__ rlogit,
        const float* __restrict__ gamma, const float* __restrict__ beta,
        float* __restrict__ out) {
    __shared__ __align__(16) __nv_bfloat16 Ks[128*16];   // 4KB
    __shared__ __align__(16) __half Vs[128*16];          // 4KB
    __shared__ __align__(16) float ctx_s[128*64];        // 32KB
    __shared__ __align__(16) u64 sWop2[20*34];           // 5.44KB
    __shared__ float sbop_s[AC];
    __shared__ float red[8][80];                         // reused by fin + ln consts
    __shared__ int s_rank;

    int b = blockIdx.y;
    int tid = threadIdx.x;
    int warp = tid >> 5, lane = tid & 31;
    int g = lane >> 2, tg = lane & 3;

    for (int i = tid; i < 20*32; i += 256) {
        int c = i >> 5, j2 = i & 31;
        sWop2[c*34 + j2] = pack2(g_Wop[c*64 + 2*j2], g_Wop[c*64 + 2*j2 + 1]);
    }
    if (tid < AC) sbop_s[tid] = g_bop[tid];

    int lrow = lane & 7, lkh = (lane >> 3) & 1, ldb = lane >> 4;
    u32 koff = (u32)(((lkh*8 + lrow)*16 + ldb*8) * 2);
    u32 kbase = smem_u32(Ks) + koff;
    u32 vbase = smem_u32(Vs) + koff;

    int qrow_local = warp*16 + g;
    int qrow = blockIdx.x*128 + qrow_local;

    // ---------- phase 1: attention, 4 heads sequential ----------
#pragma unroll 1
    for (int h = 0; h < NH; h++) {
        size_t base = ((size_t)(b*NH + h)) * Tt * HD;
        const __nv_bfloat16* Qg = g_Qh + base;
        const __nv_bfloat16* Kg = g_Kh + base;
        const __half* Vg = g_Vv + base;

        u32 a0 = *(const u32*)(Qg + (size_t)qrow*HD       + 2*tg);
        u32 a1 = *(const u32*)(Qg + (size_t)(qrow+8)*HD   + 2*tg);
        u32 a2 = *(const u32*)(Qg + (size_t)qrow*HD       + 2*tg + 8);
        u32 a3 = *(const u32*)(Qg + (size_t)(qrow+8)*HD   + 2*tg + 8);

        float l0 = 0.f, l1 = 0.f;
        float o00=0,o01=0,o02=0,o03=0, o10=0,o11=0,o12=0,o13=0;

        for (int k0 = 0; k0 < Tt; k0 += 128) {
            __syncthreads();
            {
                const float4* ksrc = (const float4*)(Kg + (size_t)k0*HD);
                const float4* vsrc = (const float4*)(Vg + (size_t)k0*HD);
                ((float4*)Ks)[tid] = ksrc[tid];
                ((float4*)Vs)[tid] = vsrc[tid];
            }
            __syncthreads();
#pragma unroll
            for (int c = 0; c < 8; c++) {
                u32 off = (u32)(c * 16 * 32);
                u32 kb0, kb1, kb2, kb3;
                ldsm4(kb0, kb1, kb2, kb3, kbase + off);
                float s00,s01,s02,s03, s10,s11,s12,s13;
                mma_bf16(s00,s01,s02,s03, a0,a1,a2,a3, kb0,kb2, 0.f,0.f,0.f,0.f);
                mma_bf16(s10,s11,s12,s13, a0,a1,a2,a3, kb1,kb3, 0.f,0.f,0.f,0.f);
                u32 p0 = cvtf16x2(s01, s00);
                u32 p1 = cvtf16x2(s03, s02);
                u32 p2 = cvtf16x2(s11, s10);
                u32 p3 = cvtf16x2(s13, s12);
                p0 = ex2h2(p0); p1 = ex2h2(p1); p2 = ex2h2(p2); p3 = ex2h2(p3);
                {
                    __half2 t02 = __hadd2(*(__half2*)&p0, *(__half2*)&p2);
                    __half2 t13 = __hadd2(*(__half2*)&p1, *(__half2*)&p3);
                    float2 f02 = __half22float2(t02);
                    float2 f13 = __half22float2(t13);
                    l0 += f02.x + f02.y;
                    l1 += f13.x + f13.y;
                }
                u32 vb0, vb1, vb2, vb3;
                ldsm4t(vb0, vb1, vb2, vb3, vbase + off);
                mma_f16(o00,o01,o02,o03, p0,p1,p2,p3, vb0,vb1, o00,o01,o02,o03);
                mma_f16(o10,o11,o12,o13, p0,p1,p2,p3, vb2,vb3, o10,o11,o12,o13);
            }
        }

        l0 += __shfl_xor_sync(0xffffffffu, l0, 1);
        l0 += __shfl_xor_sync(0xffffffffu, l0, 2);
        l1 += __shfl_xor_sync(0xffffffffu, l1, 1);
        l1 += __shfl_xor_sync(0xffffffffu, l1, 2);
        float i0 = 1.f / l0, i1 = 1.f / l1;

        float* dst0 = ctx_s + qrow_local*Hh + h*HD + 2*tg;
        dst0[0] = o00*i0; dst0[1] = o01*i0;
        dst0[8] = o10*i0; dst0[9] = o11*i0;
        float* dst1 = ctx_s + (qrow_local+8)*Hh + h*HD + 2*tg;
        dst1[0] = o02*i1; dst1[1] = o03*i1;
        dst1[8] = o12*i1; dst1[9] = o13*i1;
    }
    __syncthreads();

    // ---------- phase 2: out/proj epilogue + residual + channel stats ----------
    float sig = 1.f / (1.f + __expf(-rlogit[0]));
    bool act = lane < AC;
    int c = act ? lane : 0;
    const u64* ctx2 = (const u64*)ctx_s;
    float sa = 0.f, sa2 = 0.f, se = 0.f, se2 = 0.f;

#pragma unroll 1
    for (int half = 0; half < 2; half++) {
        int rbase = warp*16 + half*8;
        u64 acc[8];
#pragma unroll
        for (int r = 0; r < 8; r++) acc[r] = 0ull;
#pragma unroll
        for (int j4 = 0; j4 < 16; j4++) {
            ulonglong2 w = *(const ulonglong2*)&sWop2[c*34 + 2*j4];
#pragma unroll
            for (int r = 0; r < 8; r++) {
                ulonglong2 ct = *(const ulonglong2*)&ctx2[(rbase + r)*32 + 2*j4];
                acc[r] = fma2(ct.x, w.x, acc[r]);
                acc[r] = fma2(ct.y, w.y, acc[r]);
            }
        }
#pragma unroll
        for (int r = 0; r < 8; r++) {
            float lo, hi; unpack2(acc[r], lo, hi);
            float e = lo + hi + sbop_s[c];
            size_t grow = (size_t)b*Tt + blockIdx.x*128 + rbase + r;
            if (act) {
                float a = ac[grow*AC + c];
                float enh = a + sig * e;
                g_enh[grow*AC + c] = enh;
                sa += a; sa2 += a*a; se += enh; se2 += enh*enh;
            }
        }
    }
    if (act) {
        red[warp][c] = sa; red[warp][20 + c] = sa2;
        red[warp][40 + c] = se; red[warp][60 + c] = se2;
    }
    __syncthreads();
    int bid = blockIdx.y*gridDim.x + blockIdx.x;
    if (tid < 80) {
        float s = 0.f;
#pragma unroll
        for (int w = 0; w < 8; w++) s += red[w][tid];
        g_part[bid*80 + tid] = s;
    }

    // ---------- phase 3: last CTA finalizes channel stats, then raises flag ----------
    __threadfence();
    __syncthreads();
    if (tid == 0) s_rank = atomicAdd(&g_ticket, 1);
    __syncthreads();
    if (s_rank == NBLK - 1) {
        __threadfence();
        if (tid < 160) {
            int chunk = tid / 80, col = tid - chunk*80;
            float s0 = 0.f, s1 = 0.f, s2 = 0.f, s3 = 0.f;
            int base2 = chunk * 128;
            for (int blk = 0; blk < 128; blk += 4) {
                s0 += g_part[(base2+blk+0)*80 + col];
                s1 += g_part[(base2+blk+1)*80 + col];
                s2 += g_part[(base2+blk+2)*80 + col];
                s3 += g_part[(base2+blk+3)*80 + col];
            }
            red[chunk][col] = (s0 + s1) + (s2 + s3);
        }
        __syncthreads();
        if (tid < 80) red[2][tid] = red[0][tid] + red[1][tid];
        __syncthreads();
        if (tid < AC) {
            int i = tid;
            const float N = (float)NROWS;
            float sa_ = red[2][i], sa2_ = red[2][20 + i];
            float se_ = red[2][40 + i], se2_ = red[2][60 + i];
            float mean_a = sa_ / N;
            float var_a = (sa2_ - sa_*sa_ / N) / (N - 1.f);
            float std_a = sqrtf(fmaxf(var_a, 0.f));
            float orig_std = std_a + 1e-8f;
            float var_e = (se2_ - se_*se_ / N) / (N - 1.f);
            float std_e = sqrtf(fmaxf(var_e, 0.f));
            float ratio = (std_e / orig_std) / (std_a / orig_std + 1e-8f);
            float corr = (ratio < 0.4f) ? (0.4f / ratio) : 1.f;
            g_mean[i] = mean_a;
            g_corr[i] = corr;
        }
        __syncthreads();
        if (tid == 0) {
            atomicExch(&g_ticket, 0);      // reset for next replay
            __threadfence();
            atomicExch(&g_flag, 1);        // stats ready
        }
    }

    // ---------- phase 4: wait for stats, then LN on this CTA's own 128 rows ----------
    if (tid == 0) {
        while (*((volatile int*)&g_flag) == 0) __nanosleep(64);
    }
    __syncthreads();

    // ln constants into smem (reuse red)
    if (tid < AC) {
        red[0][tid] = g_mean[tid];
        red[1][tid] = g_corr[tid];
        red[2][tid] = gamma[tid];
        red[3][tid] = beta[tid];
    }
    __syncthreads();

    if (tid < 128) {
        size_t grow = (size_t)b*Tt + blockIdx.x*128 + tid;
        const float4* e4 = (const float4*)(g_enh + grow*AC);
        float4 v[5];
#pragma unroll
        for (int i = 0; i < 5; i++) v[i] = e4[i];
        const float* e = (const float*)v;
        float f[AC];
        float mu = 0.f;
#pragma unroll
        for (int cc = 0; cc < AC; cc++) {
            float x = (e[cc] - red[0][cc]) * red[1][cc] + red[0][cc];
            f[cc] = x; mu += x;
        }
        mu *= (1.f / AC);
        float var = 0.f;
#pragma unroll
        for (int cc = 0; cc < AC; cc++) { float d = f[cc] - mu; var += d*d; }
        var *= (1.f / AC);
        float rinv = rsqrtf(var + 1e-5f);
        float4 w[5];
        float* o = (float*)w;
#pragma unroll
        for (int cc = 0; cc < AC; cc++) o[cc] = (f[cc] - mu) * rinv * red[2][cc] + red[3][cc];
        float4* o4 = (float4*)(out + grow*AC);
#pragma unroll
        for (int i = 0; i < 5; i++) o4[i] = w[i];
    }

    // ---------- phase 5: last CTA to finish LN resets the flag ----------
    __syncthreads();
    if (tid == 0) {
        __threadfence();
        int old = atomicAdd(&g_passed, 1);
        if (old == NBLK - 1) {
            atomicExch(&g_flag, 0);
            atomicExch(&g_passed, 0);
        }
    }
}

// ---------------- launch ----------------
extern "C" void kernel_launch(void* const* d_in, const int* in_sizes, int n_in,
                              void* d_out, int out_size) {
    const float* acoustic = (const float*)d_in[0];
    const float* semantic = (const float*)d_in[1];
    const float* Wq   = (const float*)d_in[2];
    const float* bq   = (const float*)d_in[3];
    const float* Wkv  = (const float*)d_in[4];
    const float* bkv  = (const float*)d_in[5];
    const float* in_w = (const float*)d_in[6];
    const float* in_b = (const float*)d_in[7];
    const float* out_w = (const float*)d_in[8];
    const float* out_b = (const float*)d_in[9];
    const float* proj_w = (const float*)d_in[10];
    const float* proj_b = (const float*)d_in[11];
    const float* rlogit = (const float*)d_in[12];
    const float* gamma = (const float*)d_in[13];
    const float* beta  = (const float*)d_in[14];
    float* out = (float*)d_out;

    fuse_kernel<<<8, 256>>>(Wq, bq, Wkv, bkv, in_w, in_b, out_w, out_b, proj_w, proj_b);
    qkv_kernel<<<NROWS/128, 256>>>(semantic, acoustic);
    attn_epi_kernel<<<dim3(Tt/128, Bb), 256>>>(acoustic, rlogit, gamma, beta, out);
}